// round 1
// baseline (speedup 1.0000x reference)
#include <cuda_runtime.h>
#include <math.h>

// Problem constants
#define NB   4
#define LL   2048
#define CC   1024
#define KK   7
#define MM   (NB * LL)   // 8192

// Scratch (allocation-free rule: __device__ globals)
__device__ float g_xp[MM * CC];     // x_proj
__device__ float g_samp[MM * CC];   // sampled (pre-output-GEMM)

// ---------------------------------------------------------------------------
// SGEMM (NT): out[m,n] = sum_k A[m,k] * B[n,k] + bias[n]
// A: [Mdim, 1024] row-major, B: [1024, 1024] row-major (K contiguous in both)
// 128x128 block tile, BK=16, 8x8 per-thread micro-tile, 256 threads.
// ---------------------------------------------------------------------------
#define BM 128
#define BN 128
#define BK 16

__global__ __launch_bounds__(256, 2)
void sgemm_nt(const float* __restrict__ A, const float* __restrict__ B,
              const float* __restrict__ bias, float* __restrict__ Cout,
              int Mdim) {
    const int Kd = 1024, Nd = 1024;
    __shared__ float As[BK][BM];
    __shared__ float Bs[BK][BN];

    const int bm = blockIdx.y * BM;
    const int bn = blockIdx.x * BN;
    const int tid = threadIdx.x;
    const int tr = tid >> 4;   // 0..15
    const int tc = tid & 15;   // 0..15

    float acc[8][8];
#pragma unroll
    for (int i = 0; i < 8; ++i)
#pragma unroll
        for (int j = 0; j < 8; ++j) acc[i][j] = 0.f;

    for (int k0 = 0; k0 < Kd; k0 += BK) {
#pragma unroll
        for (int i = 0; i < 2; ++i) {
            int idx = tid + i * 256;     // 0..511
            int row = idx >> 2;          // 0..127
            int c4  = idx & 3;           // float4 slot within 16-wide row
            float4 va = *(const float4*)(&A[(size_t)(bm + row) * Kd + k0 + c4 * 4]);
            As[c4 * 4 + 0][row] = va.x;
            As[c4 * 4 + 1][row] = va.y;
            As[c4 * 4 + 2][row] = va.z;
            As[c4 * 4 + 3][row] = va.w;
            float4 vb = *(const float4*)(&B[(size_t)(bn + row) * Kd + k0 + c4 * 4]);
            Bs[c4 * 4 + 0][row] = vb.x;
            Bs[c4 * 4 + 1][row] = vb.y;
            Bs[c4 * 4 + 2][row] = vb.z;
            Bs[c4 * 4 + 3][row] = vb.w;
        }
        __syncthreads();

#pragma unroll
        for (int kk = 0; kk < BK; ++kk) {
            float a[8], b[8];
            float4 a0 = *(const float4*)(&As[kk][tr * 8]);
            float4 a1 = *(const float4*)(&As[kk][tr * 8 + 4]);
            float4 b0 = *(const float4*)(&Bs[kk][tc * 8]);
            float4 b1 = *(const float4*)(&Bs[kk][tc * 8 + 4]);
            a[0]=a0.x; a[1]=a0.y; a[2]=a0.z; a[3]=a0.w;
            a[4]=a1.x; a[5]=a1.y; a[6]=a1.z; a[7]=a1.w;
            b[0]=b0.x; b[1]=b0.y; b[2]=b0.z; b[3]=b0.w;
            b[4]=b1.x; b[5]=b1.y; b[6]=b1.z; b[7]=b1.w;
#pragma unroll
            for (int i = 0; i < 8; ++i)
#pragma unroll
                for (int j = 0; j < 8; ++j)
                    acc[i][j] = fmaf(a[i], b[j], acc[i][j]);
        }
        __syncthreads();
    }

#pragma unroll
    for (int i = 0; i < 8; ++i) {
        int m = bm + tr * 8 + i;
#pragma unroll
        for (int j = 0; j < 8; j += 4) {
            int nn = bn + tc * 8 + j;
            float4 o;
            o.x = acc[i][j + 0] + bias[nn + 0];
            o.y = acc[i][j + 1] + bias[nn + 1];
            o.z = acc[i][j + 2] + bias[nn + 2];
            o.w = acc[i][j + 3] + bias[nn + 3];
            *(float4*)(&Cout[(size_t)m * Nd + nn]) = o;
        }
    }
}

// ---------------------------------------------------------------------------
// Fused middle: depthwise conv(k=3,pad=1) + LayerNorm + exact GELU +
// offset/mask heads + softmax + position math + 14-row gather-blend.
// One block (256 thr) per (n,l); 4 channels per thread.
// ---------------------------------------------------------------------------
__global__ __launch_bounds__(256)
void fused_mid(const float* __restrict__ x,
               const float* __restrict__ dw_w, const float* __restrict__ dw_b,
               const float* __restrict__ ln_g, const float* __restrict__ ln_b,
               const float* __restrict__ Wo,   const float* __restrict__ bo,
               const float* __restrict__ Wm,   const float* __restrict__ bmv,
               const float* __restrict__ xp,   float* __restrict__ sampd) {
    const int nl = blockIdx.x;           // 0..8191
    const int n = nl >> 11;
    const int l = nl & (LL - 1);
    const int tid = threadIdx.x;
    const int lane = tid & 31;
    const int wid = tid >> 5;

    const float* x0 = x + (size_t)nl * CC;

    // depthwise conv, k=3, zero padding at sequence boundaries
    float v[4];
#pragma unroll
    for (int i = 0; i < 4; ++i) {
        int c = tid + i * 256;
        float w0 = dw_w[c * 3 + 0];
        float w1 = dw_w[c * 3 + 1];
        float w2 = dw_w[c * 3 + 2];
        float acc = dw_b[c] + x0[c] * w1;
        if (l > 0)      acc += x0[c - CC] * w0;
        if (l < LL - 1) acc += x0[c + CC] * w2;
        v[i] = acc;
    }

    // LayerNorm statistics (block reduce over 1024 channels)
    float s  = v[0] + v[1] + v[2] + v[3];
    float s2 = v[0]*v[0] + v[1]*v[1] + v[2]*v[2] + v[3]*v[3];
#pragma unroll
    for (int o = 16; o; o >>= 1) {
        s  += __shfl_xor_sync(0xFFFFFFFFu, s,  o);
        s2 += __shfl_xor_sync(0xFFFFFFFFu, s2, o);
    }
    __shared__ float rs[8], rs2[8];
    __shared__ float stats[2];
    if (lane == 0) { rs[wid] = s; rs2[wid] = s2; }
    __syncthreads();
    if (tid == 0) {
        float S = 0.f, S2 = 0.f;
#pragma unroll
        for (int w = 0; w < 8; ++w) { S += rs[w]; S2 += rs2[w]; }
        float mu = S * (1.f / CC);
        float var = S2 * (1.f / CC) - mu * mu;
        stats[0] = mu;
        stats[1] = rsqrtf(var + 1e-5f);
    }
    __syncthreads();
    const float mu = stats[0], rstd = stats[1];

    // LN affine + exact GELU
    float g[4];
#pragma unroll
    for (int i = 0; i < 4; ++i) {
        int c = tid + i * 256;
        float h = (v[i] - mu) * rstd * ln_g[c] + ln_b[c];
        g[i] = 0.5f * h * (1.f + erff(h * 0.70710678118654752f));
    }

    // offset + mask heads: 14 dot products of length 1024
    float p[14];
#pragma unroll
    for (int j = 0; j < 14; ++j) p[j] = 0.f;
#pragma unroll
    for (int i = 0; i < 4; ++i) {
        int c = tid + i * 256;
        float gg = g[i];
#pragma unroll
        for (int j = 0; j < 7; ++j) {
            p[j]     = fmaf(gg, Wo[j * CC + c], p[j]);
            p[7 + j] = fmaf(gg, Wm[j * CC + c], p[7 + j]);
        }
    }
#pragma unroll
    for (int o = 16; o; o >>= 1)
#pragma unroll
        for (int j = 0; j < 14; ++j)
            p[j] += __shfl_xor_sync(0xFFFFFFFFu, p[j], o);

    __shared__ float red[14][8];
    if (lane == 0)
#pragma unroll
        for (int j = 0; j < 14; ++j) red[j][wid] = p[j];
    __syncthreads();

    __shared__ int   spf[KK], spc[KK];
    __shared__ float swf[KK], swc[KK];
    if (tid == 0) {
        float ho[KK], hm[KK];
#pragma unroll
        for (int j = 0; j < KK; ++j) {
            float a = 0.f, b = 0.f;
#pragma unroll
            for (int w = 0; w < 8; ++w) { a += red[j][w]; b += red[7 + j][w]; }
            ho[j] = (a + bo[j]) * 2.0f;     // OFFSET_SCALE
            hm[j] = b + bmv[j];
        }
        // softmax over K
        float mx = hm[0];
#pragma unroll
        for (int j = 1; j < KK; ++j) mx = fmaxf(mx, hm[j]);
        float e[KK], se = 0.f;
#pragma unroll
        for (int j = 0; j < KK; ++j) { e[j] = expf(hm[j] - mx); se += e[j]; }
        float inv = 1.f / se;
        // positions + bilinear weights
#pragma unroll
        for (int k = 0; k < KK; ++k) {
            float mask = e[k] * inv;
            float ap  = (float)l + (float)(k - 3) + ho[k];
            float apc = fminf(fmaxf(ap, 0.f), (float)(LL - 1));
            int pf = (int)apc;                 // apc >= 0, trunc == floor
            if (pf > LL - 1) pf = LL - 1;
            int pc = pf + 1; if (pc > LL - 1) pc = LL - 1;
            float wc = apc - (float)pf;
            float wf = 1.f - wc;
            float valid = (ap < 0.f || ap > (float)(LL - 1)) ? 0.f : 1.f;
            spf[k] = pf; spc[k] = pc;
            swf[k] = wf * valid * mask;
            swc[k] = wc * valid * mask;
        }
    }
    __syncthreads();

    // gather-blend from x_proj (L2-resident)
    float o4[4] = {0.f, 0.f, 0.f, 0.f};
    const float* xpn = xp + (size_t)n * LL * CC;
#pragma unroll
    for (int k = 0; k < KK; ++k) {
        const float* rf = xpn + (size_t)spf[k] * CC;
        const float* rc = xpn + (size_t)spc[k] * CC;
        float wf = swf[k], wc = swc[k];
#pragma unroll
        for (int i = 0; i < 4; ++i) {
            int c = tid + i * 256;
            o4[i] = fmaf(rf[c], wf, o4[i]);
            o4[i] = fmaf(rc[c], wc, o4[i]);
        }
    }
    float* outr = sampd + (size_t)nl * CC;
#pragma unroll
    for (int i = 0; i < 4; ++i) outr[tid + i * 256] = o4[i];
}

// ---------------------------------------------------------------------------
// Launch
// ---------------------------------------------------------------------------
extern "C" void kernel_launch(void* const* d_in, const int* in_sizes, int n_in,
                              void* d_out, int out_size) {
    const float* x    = (const float*)d_in[0];
    const float* Wi   = (const float*)d_in[1];
    const float* bi   = (const float*)d_in[2];
    const float* dw_w = (const float*)d_in[3];
    const float* dw_b = (const float*)d_in[4];
    const float* ln_g = (const float*)d_in[5];
    const float* ln_b = (const float*)d_in[6];
    const float* Wo   = (const float*)d_in[7];
    const float* bo   = (const float*)d_in[8];
    const float* Wm   = (const float*)d_in[9];
    const float* bmv  = (const float*)d_in[10];
    const float* Wout = (const float*)d_in[11];
    const float* bout = (const float*)d_in[12];
    float* out = (float*)d_out;

    float* xp = nullptr;
    float* samp = nullptr;
    cudaGetSymbolAddress((void**)&xp, g_xp);
    cudaGetSymbolAddress((void**)&samp, g_samp);

    dim3 gemm_grid(CC / BN, MM / BM);   // (8, 64)

    // GEMM1: x_proj = x @ Wi^T + bi
    sgemm_nt<<<gemm_grid, 256>>>(x, Wi, bi, xp, MM);

    // Fused middle: conv/LN/GELU/heads/gather -> sampled
    fused_mid<<<MM, 256>>>(x, dw_w, dw_b, ln_g, ln_b, Wo, bo, Wm, bmv, xp, samp);

    // GEMM2: out = sampled @ Wout^T + bout
    sgemm_nt<<<gemm_grid, 256>>>(samp, Wout, bout, out, MM);
}

// round 3
// speedup vs baseline: 2.9164x; 2.9164x over previous
#include <cuda_runtime.h>
#include <math.h>
#include <stdint.h>

// Problem constants
#define NB   4
#define LL   2048
#define CC   1024
#define KK   7
#define MM   (NB * LL)   // 8192

// Scratch (allocation-free rule: __device__ globals)
__device__ float g_xcvt[MM * CC];   // tf32-rounded x
__device__ float g_wi[CC * CC];     // tf32-rounded Wi
__device__ float g_wo[CC * CC];     // tf32-rounded Wout
__device__ float g_xp[MM * CC];     // x_proj (fp32)
__device__ float g_samp[MM * CC];   // sampled, tf32-rounded on write

// ---------------------------------------------------------------------------
// helpers
// ---------------------------------------------------------------------------
__device__ __forceinline__ uint32_t smem_u32(const void* p) {
    uint32_t a;
    asm("{ .reg .u64 t; cvta.to.shared.u64 t, %1; cvt.u32.u64 %0, t; }"
        : "=r"(a) : "l"(p));
    return a;
}

__device__ __forceinline__ float f2tf32(float x) {
    asm("cvt.rna.tf32.f32 %0, %0;" : "+f"(x));
    return x;
}

__device__ __forceinline__ uint32_t lds32(uint32_t addr) {
    uint32_t v;
    asm volatile("ld.shared.b32 %0, [%1];" : "=r"(v) : "r"(addr));
    return v;
}

__device__ __forceinline__ void mma_tf32(float* d, const uint32_t* a,
                                         const uint32_t* b) {
    asm volatile(
        "mma.sync.aligned.m16n8k8.row.col.f32.tf32.tf32.f32 "
        "{%0,%1,%2,%3}, {%4,%5,%6,%7}, {%8,%9}, {%0,%1,%2,%3};"
        : "+f"(d[0]), "+f"(d[1]), "+f"(d[2]), "+f"(d[3])
        : "r"(a[0]), "r"(a[1]), "r"(a[2]), "r"(a[3]),
          "r"(b[0]), "r"(b[1]));
}

#define CP_ASYNC16(dst, src) \
    asm volatile("cp.async.cg.shared.global [%0], [%1], 16;" :: "r"(dst), "l"(src))
#define CP_COMMIT() asm volatile("cp.async.commit_group;" ::: "memory")
#define CP_WAIT1()  asm volatile("cp.async.wait_group 1;" ::: "memory")

// ---------------------------------------------------------------------------
// tf32 rounding pre-pass
// ---------------------------------------------------------------------------
__global__ __launch_bounds__(256)
void cvt_tf32(const float4* __restrict__ in, float4* __restrict__ out, int n4) {
    int i = blockIdx.x * blockDim.x + threadIdx.x;
    if (i < n4) {
        float4 v = in[i];
        v.x = f2tf32(v.x); v.y = f2tf32(v.y);
        v.z = f2tf32(v.z); v.w = f2tf32(v.w);
        out[i] = v;
    }
}

// ---------------------------------------------------------------------------
// tf32 mma.sync GEMM (NT): C[m,n] = sum_k A[m,k]*B[n,k] + bias[n]
// 128x128 CTA tile, BK=32, 4 warps (2x2), 64x64 warp tile.
// 3-stage cp.async pipeline, XOR-swizzled SMEM (conflict-free LDS + STS).
// A, B must be pre-rounded to tf32.
// ---------------------------------------------------------------------------
#define STAGE_BYTES 32768           // A tile 16KB + B tile 16KB
#define SMEM_DYN    (3 * STAGE_BYTES)

__device__ __forceinline__ void stage_in(uint32_t sbase,
                                         const float* __restrict__ A,
                                         const float* __restrict__ B,
                                         int bm, int bn, int k0, int tid) {
#pragma unroll
    for (int i = 0; i < 8; ++i) {
        int f = i * 128 + tid;
        int row = f >> 3, c4 = f & 7;
        uint32_t dst = sbase + row * 128 + ((c4 ^ (row & 7)) << 4);
        const float* src = A + (size_t)(bm + row) * 1024 + k0 + c4 * 4;
        CP_ASYNC16(dst, src);
    }
#pragma unroll
    for (int i = 0; i < 8; ++i) {
        int f = i * 128 + tid;
        int row = f >> 3, c4 = f & 7;
        uint32_t dst = sbase + 16384 + row * 128 + ((c4 ^ (row & 7)) << 4);
        const float* src = B + (size_t)(bn + row) * 1024 + k0 + c4 * 4;
        CP_ASYNC16(dst, src);
    }
}

__global__ __launch_bounds__(128)
void mma_gemm(const float* __restrict__ A, const float* __restrict__ B,
              const float* __restrict__ bias, float* __restrict__ Cout) {
    extern __shared__ char dyn_smem[];
    const uint32_t sb = smem_u32(dyn_smem);

    const int tid  = threadIdx.x;
    const int wid  = tid >> 5;
    const int lane = tid & 31;
    const int g    = lane >> 2;
    const int tig  = lane & 3;
    const int wm   = wid >> 1;     // 0..1
    const int wn   = wid & 1;      // 0..1
    const int bm = blockIdx.y * 128;
    const int bn = blockIdx.x * 128;

    float d[4][8][4];
#pragma unroll
    for (int i = 0; i < 4; ++i)
#pragma unroll
        for (int j = 0; j < 8; ++j)
#pragma unroll
            for (int r = 0; r < 4; ++r) d[i][j][r] = 0.f;

    // column byte-offsets within a row, swizzled, per ks
    uint32_t off0[4], off1[4];
#pragma unroll
    for (int ks = 0; ks < 4; ++ks) {
        off0[ks] = (uint32_t)(((ks * 8 + tig)     ^ (g << 2)) << 2);
        off1[ks] = (uint32_t)(((ks * 8 + tig + 4) ^ (g << 2)) << 2);
    }

    // prologue: stages 0 and 1
    stage_in(sb + 0 * STAGE_BYTES, A, B, bm, bn, 0, tid);
    CP_COMMIT();
    stage_in(sb + 1 * STAGE_BYTES, A, B, bm, bn, 32, tid);
    CP_COMMIT();

#pragma unroll 1
    for (int s = 0; s < 32; ++s) {
        CP_WAIT1();
        __syncthreads();

        if (s + 2 < 32)
            stage_in(sb + ((s + 2) % 3) * STAGE_BYTES, A, B, bm, bn,
                     (s + 2) * 32, tid);
        CP_COMMIT();

        const uint32_t base  = sb + (s % 3) * STAGE_BYTES;
        const uint32_t aBase = base + (uint32_t)((wm * 64 + g) * 128);
        const uint32_t bBase = base + 16384u + (uint32_t)((wn * 64 + g) * 128);

#pragma unroll
        for (int ks = 0; ks < 4; ++ks) {
            uint32_t af[4][4];
#pragma unroll
            for (int i = 0; i < 4; ++i) {
                uint32_t r = aBase + i * 2048;
                af[i][0] = lds32(r + off0[ks]);
                af[i][1] = lds32(r + 1024 + off0[ks]);
                af[i][2] = lds32(r + off1[ks]);
                af[i][3] = lds32(r + 1024 + off1[ks]);
            }
            uint32_t bf[8][2];
#pragma unroll
            for (int j = 0; j < 8; ++j) {
                uint32_t r = bBase + j * 1024;
                bf[j][0] = lds32(r + off0[ks]);
                bf[j][1] = lds32(r + off1[ks]);
            }
#pragma unroll
            for (int i = 0; i < 4; ++i)
#pragma unroll
                for (int j = 0; j < 8; ++j)
                    mma_tf32(d[i][j], af[i], bf[j]);
        }
    }

    // epilogue: D frag (i,j): rows (g, g+8), cols (2*tig, 2*tig+1)
#pragma unroll
    for (int i = 0; i < 4; ++i) {
        int row = bm + wm * 64 + i * 16 + g;
        float* o0 = Cout + (size_t)row * 1024 + bn + wn * 64;
        float* o1 = o0 + 8 * 1024;
#pragma unroll
        for (int j = 0; j < 8; ++j) {
            int col = j * 8 + tig * 2;
            float2 bb = *(const float2*)&bias[bn + wn * 64 + col];
            float2 v0, v1;
            v0.x = d[i][j][0] + bb.x;
            v0.y = d[i][j][1] + bb.y;
            v1.x = d[i][j][2] + bb.x;
            v1.y = d[i][j][3] + bb.y;
            *(float2*)(o0 + col) = v0;
            *(float2*)(o1 + col) = v1;
        }
    }
}

// ---------------------------------------------------------------------------
// Fused middle: depthwise conv(k=3,pad=1) + LayerNorm + exact GELU +
// offset/mask heads + softmax + position math + 14-row gather-blend.
// One block (256 thr) per (n,l); 4 channels per thread.
// Output rounded to tf32 (feeds GEMM2).
// ---------------------------------------------------------------------------
__global__ __launch_bounds__(256)
void fused_mid(const float* __restrict__ x,
               const float* __restrict__ dw_w, const float* __restrict__ dw_b,
               const float* __restrict__ ln_g, const float* __restrict__ ln_b,
               const float* __restrict__ Wo,   const float* __restrict__ bo,
               const float* __restrict__ Wm,   const float* __restrict__ bmv,
               const float* __restrict__ xp,   float* __restrict__ sampd) {
    const int nl = blockIdx.x;           // 0..8191
    const int n = nl >> 11;
    const int l = nl & (LL - 1);
    const int tid = threadIdx.x;
    const int lane = tid & 31;
    const int wid = tid >> 5;

    const float* x0 = x + (size_t)nl * CC;

    float v[4];
#pragma unroll
    for (int i = 0; i < 4; ++i) {
        int c = tid + i * 256;
        float w0 = dw_w[c * 3 + 0];
        float w1 = dw_w[c * 3 + 1];
        float w2 = dw_w[c * 3 + 2];
        float acc = dw_b[c] + x0[c] * w1;
        if (l > 0)      acc += x0[c - CC] * w0;
        if (l < LL - 1) acc += x0[c + CC] * w2;
        v[i] = acc;
    }

    float s  = v[0] + v[1] + v[2] + v[3];
    float s2 = v[0]*v[0] + v[1]*v[1] + v[2]*v[2] + v[3]*v[3];
#pragma unroll
    for (int o = 16; o; o >>= 1) {
        s  += __shfl_xor_sync(0xFFFFFFFFu, s,  o);
        s2 += __shfl_xor_sync(0xFFFFFFFFu, s2, o);
    }
    __shared__ float rs[8], rs2[8];
    __shared__ float stats[2];
    if (lane == 0) { rs[wid] = s; rs2[wid] = s2; }
    __syncthreads();
    if (tid == 0) {
        float S = 0.f, S2 = 0.f;
#pragma unroll
        for (int w = 0; w < 8; ++w) { S += rs[w]; S2 += rs2[w]; }
        float mu = S * (1.f / CC);
        float var = S2 * (1.f / CC) - mu * mu;
        stats[0] = mu;
        stats[1] = rsqrtf(var + 1e-5f);
    }
    __syncthreads();
    const float mu = stats[0], rstd = stats[1];

    float g[4];
#pragma unroll
    for (int i = 0; i < 4; ++i) {
        int c = tid + i * 256;
        float h = (v[i] - mu) * rstd * ln_g[c] + ln_b[c];
        g[i] = 0.5f * h * (1.f + erff(h * 0.70710678118654752f));
    }

    float p[14];
#pragma unroll
    for (int j = 0; j < 14; ++j) p[j] = 0.f;
#pragma unroll
    for (int i = 0; i < 4; ++i) {
        int c = tid + i * 256;
        float gg = g[i];
#pragma unroll
        for (int j = 0; j < 7; ++j) {
            p[j]     = fmaf(gg, Wo[j * CC + c], p[j]);
            p[7 + j] = fmaf(gg, Wm[j * CC + c], p[7 + j]);
        }
    }
#pragma unroll
    for (int o = 16; o; o >>= 1)
#pragma unroll
        for (int j = 0; j < 14; ++j)
            p[j] += __shfl_xor_sync(0xFFFFFFFFu, p[j], o);

    __shared__ float red[14][8];
    if (lane == 0)
#pragma unroll
        for (int j = 0; j < 14; ++j) red[j][wid] = p[j];
    __syncthreads();

    __shared__ int   spf[KK], spc[KK];
    __shared__ float swf[KK], swc[KK];
    if (tid == 0) {
        float ho[KK], hm[KK];
#pragma unroll
        for (int j = 0; j < KK; ++j) {
            float a = 0.f, b = 0.f;
#pragma unroll
            for (int w = 0; w < 8; ++w) { a += red[j][w]; b += red[7 + j][w]; }
            ho[j] = (a + bo[j]) * 2.0f;     // OFFSET_SCALE
            hm[j] = b + bmv[j];
        }
        float mx = hm[0];
#pragma unroll
        for (int j = 1; j < KK; ++j) mx = fmaxf(mx, hm[j]);
        float e[KK], se = 0.f;
#pragma unroll
        for (int j = 0; j < KK; ++j) { e[j] = expf(hm[j] - mx); se += e[j]; }
        float inv = 1.f / se;
#pragma unroll
        for (int k = 0; k < KK; ++k) {
            float mask = e[k] * inv;
            float ap  = (float)l + (float)(k - 3) + ho[k];
            float apc = fminf(fmaxf(ap, 0.f), (float)(LL - 1));
            int pf = (int)apc;
            if (pf > LL - 1) pf = LL - 1;
            int pc = pf + 1; if (pc > LL - 1) pc = LL - 1;
            float wc = apc - (float)pf;
            float wf = 1.f - wc;
            float valid = (ap < 0.f || ap > (float)(LL - 1)) ? 0.f : 1.f;
            spf[k] = pf; spc[k] = pc;
            swf[k] = wf * valid * mask;
            swc[k] = wc * valid * mask;
        }
    }
    __syncthreads();

    float o4[4] = {0.f, 0.f, 0.f, 0.f};
    const float* xpn = xp + (size_t)n * LL * CC;
#pragma unroll
    for (int k = 0; k < KK; ++k) {
        const float* rf = xpn + (size_t)spf[k] * CC;
        const float* rc = xpn + (size_t)spc[k] * CC;
        float wf = swf[k], wc = swc[k];
#pragma unroll
        for (int i = 0; i < 4; ++i) {
            int c = tid + i * 256;
            o4[i] = fmaf(rf[c], wf, o4[i]);
            o4[i] = fmaf(rc[c], wc, o4[i]);
        }
    }
    float* outr = sampd + (size_t)nl * CC;
#pragma unroll
    for (int i = 0; i < 4; ++i) outr[tid + i * 256] = f2tf32(o4[i]);
}

// ---------------------------------------------------------------------------
// Launch
// ---------------------------------------------------------------------------
extern "C" void kernel_launch(void* const* d_in, const int* in_sizes, int n_in,
                              void* d_out, int out_size) {
    const float* x    = (const float*)d_in[0];
    const float* Wi   = (const float*)d_in[1];
    const float* bi   = (const float*)d_in[2];
    const float* dw_w = (const float*)d_in[3];
    const float* dw_b = (const float*)d_in[4];
    const float* ln_g = (const float*)d_in[5];
    const float* ln_b = (const float*)d_in[6];
    const float* Wo   = (const float*)d_in[7];
    const float* bo   = (const float*)d_in[8];
    const float* Wm   = (const float*)d_in[9];
    const float* bmv  = (const float*)d_in[10];
    const float* Wout = (const float*)d_in[11];
    const float* bout = (const float*)d_in[12];
    float* out = (float*)d_out;

    float *xcvt, *wi, *wo, *xp, *samp;
    cudaGetSymbolAddress((void**)&xcvt, g_xcvt);
    cudaGetSymbolAddress((void**)&wi,   g_wi);
    cudaGetSymbolAddress((void**)&wo,   g_wo);
    cudaGetSymbolAddress((void**)&xp,   g_xp);
    cudaGetSymbolAddress((void**)&samp, g_samp);

    cudaFuncSetAttribute(mma_gemm, cudaFuncAttributeMaxDynamicSharedMemorySize,
                         SMEM_DYN);

    // tf32 round inputs/weights
    cvt_tf32<<<(MM * CC / 4) / 256, 256>>>((const float4*)x, (float4*)xcvt,
                                           MM * CC / 4);
    cvt_tf32<<<(CC * CC / 4) / 256, 256>>>((const float4*)Wi, (float4*)wi,
                                           CC * CC / 4);
    cvt_tf32<<<(CC * CC / 4) / 256, 256>>>((const float4*)Wout, (float4*)wo,
                                           CC * CC / 4);

    dim3 gemm_grid(CC / 128, MM / 128);   // (8, 64)

    // GEMM1: x_proj = x @ Wi^T + bi
    mma_gemm<<<gemm_grid, 128, SMEM_DYN>>>(xcvt, wi, bi, xp);

    // Fused middle
    fused_mid<<<MM, 256>>>(x, dw_w, dw_b, ln_g, ln_b, Wo, bo, Wm, bmv, xp, samp);

    // GEMM2: out = sampled @ Wout^T + bout
    mma_gemm<<<gemm_grid, 128, SMEM_DYN>>>(samp, wo, bout, out);
}

// round 4
// speedup vs baseline: 3.2662x; 1.1199x over previous
#include <cuda_runtime.h>
#include <math.h>
#include <stdint.h>

// Problem constants
#define NB   4
#define LL   2048
#define CC   1024
#define KK   7
#define MM   (NB * LL)   // 8192

// Scratch (allocation-free rule: __device__ globals)
__device__ float g_wi[CC * CC];     // tf32-rounded Wi
__device__ float g_wo[CC * CC];     // tf32-rounded Wout
__device__ float g_xp[MM * CC];     // x_proj (fp32)
__device__ float g_samp[MM * CC];   // sampled, tf32-rounded on write

// ---------------------------------------------------------------------------
// helpers
// ---------------------------------------------------------------------------
__device__ __forceinline__ uint32_t smem_u32(const void* p) {
    uint32_t a;
    asm("{ .reg .u64 t; cvta.to.shared.u64 t, %1; cvt.u32.u64 %0, t; }"
        : "=r"(a) : "l"(p));
    return a;
}

__device__ __forceinline__ float f2tf32(float x) {
    asm("cvt.rna.tf32.f32 %0, %0;" : "+f"(x));
    return x;
}

__device__ __forceinline__ uint32_t u2tf32(uint32_t u) {
    float f = __uint_as_float(u);
    asm("cvt.rna.tf32.f32 %0, %0;" : "+f"(f));
    return __float_as_uint(f);
}

__device__ __forceinline__ uint32_t lds32(uint32_t addr) {
    uint32_t v;
    asm volatile("ld.shared.b32 %0, [%1];" : "=r"(v) : "r"(addr));
    return v;
}

__device__ __forceinline__ void mma_tf32(float* d, const uint32_t* a,
                                         const uint32_t* b) {
    asm volatile(
        "mma.sync.aligned.m16n8k8.row.col.f32.tf32.tf32.f32 "
        "{%0,%1,%2,%3}, {%4,%5,%6,%7}, {%8,%9}, {%0,%1,%2,%3};"
        : "+f"(d[0]), "+f"(d[1]), "+f"(d[2]), "+f"(d[3])
        : "r"(a[0]), "r"(a[1]), "r"(a[2]), "r"(a[3]),
          "r"(b[0]), "r"(b[1]));
}

#define CP_ASYNC16(dst, src) \
    asm volatile("cp.async.cg.shared.global [%0], [%1], 16;" :: "r"(dst), "l"(src))
#define CP_COMMIT() asm volatile("cp.async.commit_group;" ::: "memory")
#define CP_WAIT1()  asm volatile("cp.async.wait_group 1;" ::: "memory")

// ---------------------------------------------------------------------------
// tf32 rounding pre-pass (weights only)
// ---------------------------------------------------------------------------
__global__ __launch_bounds__(256)
void cvt_tf32(const float4* __restrict__ in, float4* __restrict__ out, int n4) {
    int i = blockIdx.x * blockDim.x + threadIdx.x;
    if (i < n4) {
        float4 v = in[i];
        v.x = f2tf32(v.x); v.y = f2tf32(v.y);
        v.z = f2tf32(v.z); v.w = f2tf32(v.w);
        out[i] = v;
    }
}

// ---------------------------------------------------------------------------
// tf32 mma.sync GEMM (NT): C[m,n] = sum_k A[m,k]*B[n,k] + bias[n]
// 128x128 CTA tile, BK=32, 8 warps (4x2), 32x64 warp tile, 256 threads.
// 3-stage cp.async pipeline, XOR-swizzled SMEM (conflict-free LDS + STS).
// B must be pre-rounded to tf32; A rounded in-register when CVT_A=1.
// ---------------------------------------------------------------------------
#define STAGE_BYTES 32768           // A tile 16KB + B tile 16KB
#define SMEM_DYN    (3 * STAGE_BYTES)

__device__ __forceinline__ void stage_in(uint32_t sbase,
                                         const float* __restrict__ A,
                                         const float* __restrict__ B,
                                         int bm, int bn, int k0, int tid) {
#pragma unroll
    for (int i = 0; i < 4; ++i) {
        int f = i * 256 + tid;
        int row = f >> 3, c4 = f & 7;
        uint32_t dst = sbase + row * 128 + ((c4 ^ (row & 7)) << 4);
        const float* src = A + (size_t)(bm + row) * 1024 + k0 + c4 * 4;
        CP_ASYNC16(dst, src);
    }
#pragma unroll
    for (int i = 0; i < 4; ++i) {
        int f = i * 256 + tid;
        int row = f >> 3, c4 = f & 7;
        uint32_t dst = sbase + 16384 + row * 128 + ((c4 ^ (row & 7)) << 4);
        const float* src = B + (size_t)(bn + row) * 1024 + k0 + c4 * 4;
        CP_ASYNC16(dst, src);
    }
}

template <int CVT_A>
__global__ __launch_bounds__(256, 2)
void mma_gemm(const float* __restrict__ A, const float* __restrict__ B,
              const float* __restrict__ bias, float* __restrict__ Cout) {
    extern __shared__ char dyn_smem[];
    const uint32_t sb = smem_u32(dyn_smem);

    const int tid  = threadIdx.x;
    const int wid  = tid >> 5;
    const int lane = tid & 31;
    const int g    = lane >> 2;
    const int tig  = lane & 3;
    const int wm   = wid >> 1;     // 0..3  (32 rows each)
    const int wn   = wid & 1;      // 0..1  (64 cols each)
    const int bm = blockIdx.y * 128;
    const int bn = blockIdx.x * 128;

    float d[2][8][4];
#pragma unroll
    for (int i = 0; i < 2; ++i)
#pragma unroll
        for (int j = 0; j < 8; ++j)
#pragma unroll
            for (int r = 0; r < 4; ++r) d[i][j][r] = 0.f;

    // column byte-offsets within a row, swizzled, per ks
    uint32_t off0[4], off1[4];
#pragma unroll
    for (int ks = 0; ks < 4; ++ks) {
        off0[ks] = (uint32_t)(((ks * 8 + tig)     ^ (g << 2)) << 2);
        off1[ks] = (uint32_t)(((ks * 8 + tig + 4) ^ (g << 2)) << 2);
    }

    // prologue: stages 0 and 1
    stage_in(sb + 0 * STAGE_BYTES, A, B, bm, bn, 0, tid);
    CP_COMMIT();
    stage_in(sb + 1 * STAGE_BYTES, A, B, bm, bn, 32, tid);
    CP_COMMIT();

#pragma unroll 1
    for (int s = 0; s < 32; ++s) {
        CP_WAIT1();
        __syncthreads();

        if (s + 2 < 32)
            stage_in(sb + ((s + 2) % 3) * STAGE_BYTES, A, B, bm, bn,
                     (s + 2) * 32, tid);
        CP_COMMIT();

        const uint32_t base  = sb + (s % 3) * STAGE_BYTES;
        const uint32_t aBase = base + (uint32_t)((wm * 32 + g) * 128);
        const uint32_t bBase = base + 16384u + (uint32_t)((wn * 64 + g) * 128);

#pragma unroll
        for (int ks = 0; ks < 4; ++ks) {
            uint32_t af[2][4];
#pragma unroll
            for (int i = 0; i < 2; ++i) {
                uint32_t r = aBase + i * 2048;
                af[i][0] = lds32(r + off0[ks]);
                af[i][1] = lds32(r + 1024 + off0[ks]);
                af[i][2] = lds32(r + off1[ks]);
                af[i][3] = lds32(r + 1024 + off1[ks]);
                if (CVT_A) {
                    af[i][0] = u2tf32(af[i][0]);
                    af[i][1] = u2tf32(af[i][1]);
                    af[i][2] = u2tf32(af[i][2]);
                    af[i][3] = u2tf32(af[i][3]);
                }
            }
            uint32_t bf[8][2];
#pragma unroll
            for (int j = 0; j < 8; ++j) {
                uint32_t r = bBase + j * 1024;
                bf[j][0] = lds32(r + off0[ks]);
                bf[j][1] = lds32(r + off1[ks]);
            }
#pragma unroll
            for (int i = 0; i < 2; ++i)
#pragma unroll
                for (int j = 0; j < 8; ++j)
                    mma_tf32(d[i][j], af[i], bf[j]);
        }
    }

    // epilogue: D frag (i,j): rows (g, g+8), cols (2*tig, 2*tig+1)
#pragma unroll
    for (int i = 0; i < 2; ++i) {
        int row = bm + wm * 32 + i * 16 + g;
        float* o0 = Cout + (size_t)row * 1024 + bn + wn * 64;
        float* o1 = o0 + 8 * 1024;
#pragma unroll
        for (int j = 0; j < 8; ++j) {
            int col = j * 8 + tig * 2;
            float2 bb = *(const float2*)&bias[bn + wn * 64 + col];
            float2 v0, v1;
            v0.x = d[i][j][0] + bb.x;
            v0.y = d[i][j][1] + bb.y;
            v1.x = d[i][j][2] + bb.x;
            v1.y = d[i][j][3] + bb.y;
            *(float2*)(o0 + col) = v0;
            *(float2*)(o1 + col) = v1;
        }
    }
}

// ---------------------------------------------------------------------------
// Fused middle: depthwise conv(k=3,pad=1) + LayerNorm + exact GELU +
// offset/mask heads + softmax + position math + 14-row gather-blend.
// One block (256 thr) per (n,l); float4 per thread (channels 4t..4t+3).
// Output rounded to tf32 (feeds GEMM2).
// ---------------------------------------------------------------------------
__global__ __launch_bounds__(256)
void fused_mid(const float* __restrict__ x,
               const float* __restrict__ dw_w, const float* __restrict__ dw_b,
               const float* __restrict__ ln_g, const float* __restrict__ ln_b,
               const float* __restrict__ Wo,   const float* __restrict__ bo,
               const float* __restrict__ Wm,   const float* __restrict__ bmv,
               const float* __restrict__ xp,   float* __restrict__ sampd) {
    const int nl = blockIdx.x;           // 0..8191
    const int n = nl >> 11;
    const int l = nl & (LL - 1);
    const int tid = threadIdx.x;
    const int lane = tid & 31;
    const int wid = tid >> 5;
    const int c0 = tid * 4;

    const float* x0 = x + (size_t)nl * CC;

    // depthwise conv, k=3, zero padding at sequence boundaries
    float4 xm = *(const float4*)(x0 + c0);
    float4 xl = (l > 0)      ? *(const float4*)(x0 + c0 - CC) : make_float4(0,0,0,0);
    float4 xr = (l < LL - 1) ? *(const float4*)(x0 + c0 + CC) : make_float4(0,0,0,0);
    float4 db = *(const float4*)(dw_b + c0);
    float v[4];
    {
        const float* wp = dw_w + c0 * 3;
        v[0] = db.x + xl.x * wp[0]  + xm.x * wp[1]  + xr.x * wp[2];
        v[1] = db.y + xl.y * wp[3]  + xm.y * wp[4]  + xr.y * wp[5];
        v[2] = db.z + xl.z * wp[6]  + xm.z * wp[7]  + xr.z * wp[8];
        v[3] = db.w + xl.w * wp[9]  + xm.w * wp[10] + xr.w * wp[11];
    }

    // LayerNorm statistics (block reduce over 1024 channels)
    float s  = v[0] + v[1] + v[2] + v[3];
    float s2 = v[0]*v[0] + v[1]*v[1] + v[2]*v[2] + v[3]*v[3];
#pragma unroll
    for (int o = 16; o; o >>= 1) {
        s  += __shfl_xor_sync(0xFFFFFFFFu, s,  o);
        s2 += __shfl_xor_sync(0xFFFFFFFFu, s2, o);
    }
    __shared__ float rs[8], rs2[8];
    __shared__ float stats[2];
    if (lane == 0) { rs[wid] = s; rs2[wid] = s2; }
    __syncthreads();
    if (tid == 0) {
        float S = 0.f, S2 = 0.f;
#pragma unroll
        for (int w = 0; w < 8; ++w) { S += rs[w]; S2 += rs2[w]; }
        float mu = S * (1.f / CC);
        float var = S2 * (1.f / CC) - mu * mu;
        stats[0] = mu;
        stats[1] = rsqrtf(var + 1e-5f);
    }
    __syncthreads();
    const float mu = stats[0], rstd = stats[1];

    // LN affine + exact GELU
    float4 lg = *(const float4*)(ln_g + c0);
    float4 lb = *(const float4*)(ln_b + c0);
    float g4[4];
    {
        float h;
        h = (v[0] - mu) * rstd * lg.x + lb.x;
        g4[0] = 0.5f * h * (1.f + erff(h * 0.70710678118654752f));
        h = (v[1] - mu) * rstd * lg.y + lb.y;
        g4[1] = 0.5f * h * (1.f + erff(h * 0.70710678118654752f));
        h = (v[2] - mu) * rstd * lg.z + lb.z;
        g4[2] = 0.5f * h * (1.f + erff(h * 0.70710678118654752f));
        h = (v[3] - mu) * rstd * lg.w + lb.w;
        g4[3] = 0.5f * h * (1.f + erff(h * 0.70710678118654752f));
    }

    // offset + mask heads: 14 dot products of length 1024
    float p[14];
#pragma unroll
    for (int j = 0; j < 7; ++j) {
        float4 w1 = *(const float4*)(Wo + j * CC + c0);
        float4 w2 = *(const float4*)(Wm + j * CC + c0);
        p[j] = g4[0]*w1.x + g4[1]*w1.y + g4[2]*w1.z + g4[3]*w1.w;
        p[7+j] = g4[0]*w2.x + g4[1]*w2.y + g4[2]*w2.z + g4[3]*w2.w;
    }
#pragma unroll
    for (int o = 16; o; o >>= 1)
#pragma unroll
        for (int j = 0; j < 14; ++j)
            p[j] += __shfl_xor_sync(0xFFFFFFFFu, p[j], o);

    __shared__ float red[14][8];
    if (lane == 0)
#pragma unroll
        for (int j = 0; j < 14; ++j) red[j][wid] = p[j];
    __syncthreads();

    __shared__ int   spf[KK], spc[KK];
    __shared__ float swf[KK], swc[KK];
    if (tid == 0) {
        float ho[KK], hm[KK];
#pragma unroll
        for (int j = 0; j < KK; ++j) {
            float a = 0.f, b = 0.f;
#pragma unroll
            for (int w = 0; w < 8; ++w) { a += red[j][w]; b += red[7 + j][w]; }
            ho[j] = (a + bo[j]) * 2.0f;     // OFFSET_SCALE
            hm[j] = b + bmv[j];
        }
        // softmax over K
        float mx = hm[0];
#pragma unroll
        for (int j = 1; j < KK; ++j) mx = fmaxf(mx, hm[j]);
        float e[KK], se = 0.f;
#pragma unroll
        for (int j = 0; j < KK; ++j) { e[j] = expf(hm[j] - mx); se += e[j]; }
        float inv = 1.f / se;
#pragma unroll
        for (int k = 0; k < KK; ++k) {
            float mask = e[k] * inv;
            float ap  = (float)l + (float)(k - 3) + ho[k];
            float apc = fminf(fmaxf(ap, 0.f), (float)(LL - 1));
            int pf = (int)apc;
            if (pf > LL - 1) pf = LL - 1;
            int pc = pf + 1; if (pc > LL - 1) pc = LL - 1;
            float wc = apc - (float)pf;
            float wf = 1.f - wc;
            float valid = (ap < 0.f || ap > (float)(LL - 1)) ? 0.f : 1.f;
            spf[k] = pf; spc[k] = pc;
            swf[k] = wf * valid * mask;
            swc[k] = wc * valid * mask;
        }
    }
    __syncthreads();

    // gather-blend from x_proj (L2-resident)
    float o0 = 0.f, o1 = 0.f, o2 = 0.f, o3 = 0.f;
    const float* xpn = xp + (size_t)n * LL * CC;
#pragma unroll
    for (int k = 0; k < KK; ++k) {
        float4 rf = *(const float4*)(xpn + (size_t)spf[k] * CC + c0);
        float4 rc = *(const float4*)(xpn + (size_t)spc[k] * CC + c0);
        float wf = swf[k], wc = swc[k];
        o0 = fmaf(rf.x, wf, fmaf(rc.x, wc, o0));
        o1 = fmaf(rf.y, wf, fmaf(rc.y, wc, o1));
        o2 = fmaf(rf.z, wf, fmaf(rc.z, wc, o2));
        o3 = fmaf(rf.w, wf, fmaf(rc.w, wc, o3));
    }
    float4 ov;
    ov.x = f2tf32(o0); ov.y = f2tf32(o1);
    ov.z = f2tf32(o2); ov.w = f2tf32(o3);
    *(float4*)(sampd + (size_t)nl * CC + c0) = ov;
}

// ---------------------------------------------------------------------------
// Launch
// ---------------------------------------------------------------------------
extern "C" void kernel_launch(void* const* d_in, const int* in_sizes, int n_in,
                              void* d_out, int out_size) {
    const float* x    = (const float*)d_in[0];
    const float* Wi   = (const float*)d_in[1];
    const float* bi   = (const float*)d_in[2];
    const float* dw_w = (const float*)d_in[3];
    const float* dw_b = (const float*)d_in[4];
    const float* ln_g = (const float*)d_in[5];
    const float* ln_b = (const float*)d_in[6];
    const float* Wo   = (const float*)d_in[7];
    const float* bo   = (const float*)d_in[8];
    const float* Wm   = (const float*)d_in[9];
    const float* bmv  = (const float*)d_in[10];
    const float* Wout = (const float*)d_in[11];
    const float* bout = (const float*)d_in[12];
    float* out = (float*)d_out;

    float *wi, *wo, *xp, *samp;
    cudaGetSymbolAddress((void**)&wi,   g_wi);
    cudaGetSymbolAddress((void**)&wo,   g_wo);
    cudaGetSymbolAddress((void**)&xp,   g_xp);
    cudaGetSymbolAddress((void**)&samp, g_samp);

    cudaFuncSetAttribute(mma_gemm<0>, cudaFuncAttributeMaxDynamicSharedMemorySize,
                         SMEM_DYN);
    cudaFuncSetAttribute(mma_gemm<1>, cudaFuncAttributeMaxDynamicSharedMemorySize,
                         SMEM_DYN);

    // tf32 round weights (x handled in-register inside GEMM1)
    cvt_tf32<<<(CC * CC / 4) / 256, 256>>>((const float4*)Wi, (float4*)wi,
                                           CC * CC / 4);
    cvt_tf32<<<(CC * CC / 4) / 256, 256>>>((const float4*)Wout, (float4*)wo,
                                           CC * CC / 4);

    dim3 gemm_grid(CC / 128, MM / 128);   // (8, 64)

    // GEMM1: x_proj = x @ Wi^T + bi  (A rounded in-register)
    mma_gemm<1><<<gemm_grid, 256, SMEM_DYN>>>(x, wi, bi, xp);

    // Fused middle
    fused_mid<<<MM, 256>>>(x, dw_w, dw_b, ln_g, ln_b, Wo, bo, Wm, bmv, xp, samp);

    // GEMM2: out = sampled @ Wout^T + bout  (A pre-rounded by fused_mid)
    mma_gemm<0><<<gemm_grid, 256, SMEM_DYN>>>(samp, wo, bout, out);
}

// round 5
// speedup vs baseline: 3.5997x; 1.1021x over previous
#include <cuda_runtime.h>
#include <cuda_fp16.h>
#include <math.h>
#include <stdint.h>

// Problem constants
#define NB   4
#define LL   2048
#define CC   1024
#define KK   7
#define MM   (NB * LL)   // 8192

// Scratch (allocation-free rule: __device__ globals)
__device__ __half g_xh[MM * CC];     // fp16 x
__device__ __half g_wih[CC * CC];    // fp16 Wi
__device__ __half g_woh[CC * CC];    // fp16 Wout
__device__ float  g_xp[MM * CC];     // x_proj (fp32)
__device__ __half g_samph[MM * CC];  // sampled (fp16)

// ---------------------------------------------------------------------------
// helpers
// ---------------------------------------------------------------------------
__device__ __forceinline__ uint32_t smem_u32(const void* p) {
    uint32_t a;
    asm("{ .reg .u64 t; cvta.to.shared.u64 t, %1; cvt.u32.u64 %0, t; }"
        : "=r"(a) : "l"(p));
    return a;
}

__device__ __forceinline__ uint32_t lds32(uint32_t addr) {
    uint32_t v;
    asm volatile("ld.shared.b32 %0, [%1];" : "=r"(v) : "r"(addr));
    return v;
}

__device__ __forceinline__ void mma_f16(float* d, const uint32_t* a,
                                        const uint32_t* b) {
    asm volatile(
        "mma.sync.aligned.m16n8k16.row.col.f32.f16.f16.f32 "
        "{%0,%1,%2,%3}, {%4,%5,%6,%7}, {%8,%9}, {%0,%1,%2,%3};"
        : "+f"(d[0]), "+f"(d[1]), "+f"(d[2]), "+f"(d[3])
        : "r"(a[0]), "r"(a[1]), "r"(a[2]), "r"(a[3]),
          "r"(b[0]), "r"(b[1]));
}

#define CP_ASYNC16(dst, src) \
    asm volatile("cp.async.cg.shared.global [%0], [%1], 16;" :: "r"(dst), "l"(src))
#define CP_COMMIT() asm volatile("cp.async.commit_group;" ::: "memory")
#define CP_WAIT1()  asm volatile("cp.async.wait_group 1;" ::: "memory")

// ---------------------------------------------------------------------------
// fp32 -> fp16 conversion pre-pass
// ---------------------------------------------------------------------------
__global__ __launch_bounds__(256)
void cvt_f16(const float4* __restrict__ in, uint2* __restrict__ out, int n4) {
    int i = blockIdx.x * blockDim.x + threadIdx.x;
    if (i < n4) {
        float4 v = in[i];
        __half2 h0 = __floats2half2_rn(v.x, v.y);
        __half2 h1 = __floats2half2_rn(v.z, v.w);
        uint2 o;
        o.x = *(uint32_t*)&h0;
        o.y = *(uint32_t*)&h1;
        out[i] = o;
    }
}

// ---------------------------------------------------------------------------
// fp16 mma.sync GEMM (NT): C[m,n] = sum_k A[m,k]*B[n,k] + bias[n]
// A,B fp16 [.,1024]; 128x128 CTA tile, BK=64 (128B rows), 8 warps (4x2),
// 32x64 warp tile, 256 threads, 3-stage cp.async, XOR swizzle.
// ---------------------------------------------------------------------------
#define STAGE_BYTES 32768           // A tile 16KB + B tile 16KB
#define SMEM_DYN    (3 * STAGE_BYTES)

__device__ __forceinline__ void stage_in(uint32_t sbase,
                                         const __half* __restrict__ A,
                                         const __half* __restrict__ B,
                                         int bm, int bn, int k0, int tid) {
#pragma unroll
    for (int i = 0; i < 4; ++i) {
        int f = i * 256 + tid;            // 0..1023
        int row = f >> 3, c4 = f & 7;
        uint32_t dst = sbase + row * 128 + ((c4 ^ (row & 7)) << 4);
        const __half* src = A + (size_t)(bm + row) * 1024 + k0 + c4 * 8;
        CP_ASYNC16(dst, src);
    }
#pragma unroll
    for (int i = 0; i < 4; ++i) {
        int f = i * 256 + tid;
        int row = f >> 3, c4 = f & 7;
        uint32_t dst = sbase + 16384 + row * 128 + ((c4 ^ (row & 7)) << 4);
        const __half* src = B + (size_t)(bn + row) * 1024 + k0 + c4 * 8;
        CP_ASYNC16(dst, src);
    }
}

__global__ __launch_bounds__(256, 2)
void mma_gemm(const __half* __restrict__ A, const __half* __restrict__ B,
              const float* __restrict__ bias, float* __restrict__ Cout) {
    extern __shared__ char dyn_smem[];
    const uint32_t sb = smem_u32(dyn_smem);

    const int tid  = threadIdx.x;
    const int wid  = tid >> 5;
    const int lane = tid & 31;
    const int g    = lane >> 2;
    const int tig  = lane & 3;
    const int wm   = wid >> 1;     // 0..3  (32 rows each)
    const int wn   = wid & 1;      // 0..1  (64 cols each)
    const int bm = blockIdx.y * 128;
    const int bn = blockIdx.x * 128;

    float d[2][8][4];
#pragma unroll
    for (int i = 0; i < 2; ++i)
#pragma unroll
        for (int j = 0; j < 8; ++j)
#pragma unroll
            for (int r = 0; r < 4; ++r) d[i][j][r] = 0.f;

    // swizzled byte offsets within a row, per K16 step ks (granule 2ks, 2ks+1)
    uint32_t off0[4], off1[4];
#pragma unroll
    for (int ks = 0; ks < 4; ++ks) {
        off0[ks] = (uint32_t)((((2 * ks)     ^ g) << 4) + 4 * tig);
        off1[ks] = (uint32_t)((((2 * ks + 1) ^ g) << 4) + 4 * tig);
    }

    // prologue
    stage_in(sb + 0 * STAGE_BYTES, A, B, bm, bn, 0, tid);
    CP_COMMIT();
    stage_in(sb + 1 * STAGE_BYTES, A, B, bm, bn, 64, tid);
    CP_COMMIT();

#pragma unroll 1
    for (int s = 0; s < 16; ++s) {
        CP_WAIT1();
        __syncthreads();

        if (s + 2 < 16)
            stage_in(sb + ((s + 2) % 3) * STAGE_BYTES, A, B, bm, bn,
                     (s + 2) * 64, tid);
        CP_COMMIT();

        const uint32_t base  = sb + (s % 3) * STAGE_BYTES;
        const uint32_t aBase = base + (uint32_t)((wm * 32 + g) * 128);
        const uint32_t bBase = base + 16384u + (uint32_t)((wn * 64 + g) * 128);

#pragma unroll
        for (int ks = 0; ks < 4; ++ks) {
            uint32_t af[2][4];
#pragma unroll
            for (int i = 0; i < 2; ++i) {
                uint32_t r = aBase + i * 2048;
                af[i][0] = lds32(r + off0[ks]);
                af[i][1] = lds32(r + 1024 + off0[ks]);
                af[i][2] = lds32(r + off1[ks]);
                af[i][3] = lds32(r + 1024 + off1[ks]);
            }
            uint32_t bf[8][2];
#pragma unroll
            for (int j = 0; j < 8; ++j) {
                uint32_t r = bBase + j * 1024;
                bf[j][0] = lds32(r + off0[ks]);
                bf[j][1] = lds32(r + off1[ks]);
            }
#pragma unroll
            for (int i = 0; i < 2; ++i)
#pragma unroll
                for (int j = 0; j < 8; ++j)
                    mma_f16(d[i][j], af[i], bf[j]);
        }
    }

    // epilogue: D frag (i,j): rows (g, g+8), cols (2*tig, 2*tig+1)
#pragma unroll
    for (int i = 0; i < 2; ++i) {
        int row = bm + wm * 32 + i * 16 + g;
        float* o0 = Cout + (size_t)row * 1024 + bn + wn * 64;
        float* o1 = o0 + 8 * 1024;
#pragma unroll
        for (int j = 0; j < 8; ++j) {
            int col = j * 8 + tig * 2;
            float2 bb = *(const float2*)&bias[bn + wn * 64 + col];
            float2 v0, v1;
            v0.x = d[i][j][0] + bb.x;
            v0.y = d[i][j][1] + bb.y;
            v1.x = d[i][j][2] + bb.x;
            v1.y = d[i][j][3] + bb.y;
            *(float2*)(o0 + col) = v0;
            *(float2*)(o1 + col) = v1;
        }
    }
}

// ---------------------------------------------------------------------------
// Fused middle, P=4 positions per block.
// depthwise conv(k=3,pad=1) + LayerNorm + exact GELU + heads + softmax +
// positions + 14-row gather-blend. 256 threads; channels 4t..4t+3 per thread.
// Weights held in registers across positions; conv rows rotated.
// Output written as fp16 (feeds GEMM2).
// ---------------------------------------------------------------------------
__global__ __launch_bounds__(256)
void fused_mid(const float* __restrict__ x,
               const float* __restrict__ dw_w, const float* __restrict__ dw_b,
               const float* __restrict__ ln_g, const float* __restrict__ ln_b,
               const float* __restrict__ Wo,   const float* __restrict__ bo,
               const float* __restrict__ Wm,   const float* __restrict__ bmv,
               const float* __restrict__ xp,   __half* __restrict__ sampd) {
    const int nl0 = blockIdx.x * 4;      // 0..8188
    const int n  = nl0 >> 11;
    const int l0 = nl0 & (LL - 1);
    const int tid = threadIdx.x;
    const int lane = tid & 31;
    const int wid = tid >> 5;
    const int c0 = tid * 4;

    // ---- weights in registers ----
    float4 q0 = *(const float4*)(dw_w + c0 * 3);
    float4 q1 = *(const float4*)(dw_w + c0 * 3 + 4);
    float4 q2 = *(const float4*)(dw_w + c0 * 3 + 8);
    // wv[ch][tap]: ch0:{q0.x,q0.y,q0.z} ch1:{q0.w,q1.x,q1.y}
    //              ch2:{q1.z,q1.w,q2.x} ch3:{q2.y,q2.z,q2.w}
    float4 dbv = *(const float4*)(dw_b + c0);
    float4 lg  = *(const float4*)(ln_g + c0);
    float4 lb  = *(const float4*)(ln_b + c0);
    float4 wo_r[7], wm_r[7];
#pragma unroll
    for (int j = 0; j < 7; ++j) {
        wo_r[j] = *(const float4*)(Wo + j * CC + c0);
        wm_r[j] = *(const float4*)(Wm + j * CC + c0);
    }

    __shared__ float rs[8], rs2[8], stats[2], red[14][8];
    __shared__ int   spf[KK], spc[KK];
    __shared__ float swf[KK], swc[KK];

    const float* xb  = x + (size_t)nl0 * CC + c0;
    const float* xpn = xp + (size_t)n * LL * CC;

    float4 xl = (l0 > 0) ? *(const float4*)(xb - CC)
                         : make_float4(0.f, 0.f, 0.f, 0.f);
    float4 xm = *(const float4*)(xb);

#pragma unroll 1
    for (int p = 0; p < 4; ++p) {
        const int l  = l0 + p;
        const int nl = nl0 + p;
        float4 xr = (l < LL - 1) ? *(const float4*)(xb + (p + 1) * CC)
                                 : make_float4(0.f, 0.f, 0.f, 0.f);

        // depthwise conv
        float v0 = dbv.x + xl.x * q0.x + xm.x * q0.y + xr.x * q0.z;
        float v1 = dbv.y + xl.y * q0.w + xm.y * q1.x + xr.y * q1.y;
        float v2 = dbv.z + xl.z * q1.z + xm.z * q1.w + xr.z * q2.x;
        float v3 = dbv.w + xl.w * q2.y + xm.w * q2.z + xr.w * q2.w;

        // LN stats
        float s  = v0 + v1 + v2 + v3;
        float s2 = v0*v0 + v1*v1 + v2*v2 + v3*v3;
#pragma unroll
        for (int o = 16; o; o >>= 1) {
            s  += __shfl_xor_sync(0xFFFFFFFFu, s,  o);
            s2 += __shfl_xor_sync(0xFFFFFFFFu, s2, o);
        }
        if (lane == 0) { rs[wid] = s; rs2[wid] = s2; }
        __syncthreads();
        if (tid == 0) {
            float S = 0.f, S2 = 0.f;
#pragma unroll
            for (int w = 0; w < 8; ++w) { S += rs[w]; S2 += rs2[w]; }
            float mu = S * (1.f / CC);
            float var = S2 * (1.f / CC) - mu * mu;
            stats[0] = mu;
            stats[1] = rsqrtf(var + 1e-5f);
        }
        __syncthreads();
        const float mu = stats[0], rstd = stats[1];

        // LN affine + exact GELU
        float g4[4];
        {
            float h;
            h = (v0 - mu) * rstd * lg.x + lb.x;
            g4[0] = 0.5f * h * (1.f + erff(h * 0.70710678118654752f));
            h = (v1 - mu) * rstd * lg.y + lb.y;
            g4[1] = 0.5f * h * (1.f + erff(h * 0.70710678118654752f));
            h = (v2 - mu) * rstd * lg.z + lb.z;
            g4[2] = 0.5f * h * (1.f + erff(h * 0.70710678118654752f));
            h = (v3 - mu) * rstd * lg.w + lb.w;
            g4[3] = 0.5f * h * (1.f + erff(h * 0.70710678118654752f));
        }

        // heads: 14 dots
        float pr[14];
#pragma unroll
        for (int j = 0; j < 7; ++j) {
            float4 w1 = wo_r[j], w2 = wm_r[j];
            pr[j]   = g4[0]*w1.x + g4[1]*w1.y + g4[2]*w1.z + g4[3]*w1.w;
            pr[7+j] = g4[0]*w2.x + g4[1]*w2.y + g4[2]*w2.z + g4[3]*w2.w;
        }
#pragma unroll
        for (int o = 16; o; o >>= 1)
#pragma unroll
            for (int j = 0; j < 14; ++j)
                pr[j] += __shfl_xor_sync(0xFFFFFFFFu, pr[j], o);
        if (lane == 0)
#pragma unroll
            for (int j = 0; j < 14; ++j) red[j][wid] = pr[j];
        __syncthreads();

        if (tid == 0) {
            float ho[KK], hm[KK];
#pragma unroll
            for (int j = 0; j < KK; ++j) {
                float a = 0.f, b = 0.f;
#pragma unroll
                for (int w = 0; w < 8; ++w) { a += red[j][w]; b += red[7 + j][w]; }
                ho[j] = (a + bo[j]) * 2.0f;     // OFFSET_SCALE
                hm[j] = b + bmv[j];
            }
            float mx = hm[0];
#pragma unroll
            for (int j = 1; j < KK; ++j) mx = fmaxf(mx, hm[j]);
            float e[KK], se = 0.f;
#pragma unroll
            for (int j = 0; j < KK; ++j) { e[j] = expf(hm[j] - mx); se += e[j]; }
            float inv = 1.f / se;
#pragma unroll
            for (int k = 0; k < KK; ++k) {
                float mask = e[k] * inv;
                float ap  = (float)l + (float)(k - 3) + ho[k];
                float apc = fminf(fmaxf(ap, 0.f), (float)(LL - 1));
                int pf = (int)apc;
                if (pf > LL - 1) pf = LL - 1;
                int pc = pf + 1; if (pc > LL - 1) pc = LL - 1;
                float wcc = apc - (float)pf;
                float wff = 1.f - wcc;
                float valid = (ap < 0.f || ap > (float)(LL - 1)) ? 0.f : 1.f;
                spf[k] = pf; spc[k] = pc;
                swf[k] = wff * valid * mask;
                swc[k] = wcc * valid * mask;
            }
        }
        __syncthreads();

        // gather-blend from x_proj
        float o0 = 0.f, o1 = 0.f, o2 = 0.f, o3 = 0.f;
#pragma unroll
        for (int k = 0; k < KK; ++k) {
            float4 rf = *(const float4*)(xpn + (size_t)spf[k] * CC + c0);
            float4 rc = *(const float4*)(xpn + (size_t)spc[k] * CC + c0);
            float wf = swf[k], wc = swc[k];
            o0 = fmaf(rf.x, wf, fmaf(rc.x, wc, o0));
            o1 = fmaf(rf.y, wf, fmaf(rc.y, wc, o1));
            o2 = fmaf(rf.z, wf, fmaf(rc.z, wc, o2));
            o3 = fmaf(rf.w, wf, fmaf(rc.w, wc, o3));
        }
        __half2 h0 = __floats2half2_rn(o0, o1);
        __half2 h1 = __floats2half2_rn(o2, o3);
        uint2 ov;
        ov.x = *(uint32_t*)&h0;
        ov.y = *(uint32_t*)&h1;
        *(uint2*)(sampd + (size_t)nl * CC + c0) = ov;

        __syncthreads();   // smem reuse guard
        xl = xm; xm = xr;
    }
}

// ---------------------------------------------------------------------------
// Launch
// ---------------------------------------------------------------------------
extern "C" void kernel_launch(void* const* d_in, const int* in_sizes, int n_in,
                              void* d_out, int out_size) {
    const float* x    = (const float*)d_in[0];
    const float* Wi   = (const float*)d_in[1];
    const float* bi   = (const float*)d_in[2];
    const float* dw_w = (const float*)d_in[3];
    const float* dw_b = (const float*)d_in[4];
    const float* ln_g = (const float*)d_in[5];
    const float* ln_b = (const float*)d_in[6];
    const float* Wo   = (const float*)d_in[7];
    const float* bo   = (const float*)d_in[8];
    const float* Wm   = (const float*)d_in[9];
    const float* bmv  = (const float*)d_in[10];
    const float* Wout = (const float*)d_in[11];
    const float* bout = (const float*)d_in[12];
    float* out = (float*)d_out;

    __half *xh, *wih, *woh, *samph;
    float *xp;
    cudaGetSymbolAddress((void**)&xh,    g_xh);
    cudaGetSymbolAddress((void**)&wih,   g_wih);
    cudaGetSymbolAddress((void**)&woh,   g_woh);
    cudaGetSymbolAddress((void**)&xp,    g_xp);
    cudaGetSymbolAddress((void**)&samph, g_samph);

    cudaFuncSetAttribute(mma_gemm, cudaFuncAttributeMaxDynamicSharedMemorySize,
                         SMEM_DYN);

    // fp16 conversions
    cvt_f16<<<(MM * CC / 4) / 256, 256>>>((const float4*)x, (uint2*)xh,
                                          MM * CC / 4);
    cvt_f16<<<(CC * CC / 4) / 256, 256>>>((const float4*)Wi, (uint2*)wih,
                                          CC * CC / 4);
    cvt_f16<<<(CC * CC / 4) / 256, 256>>>((const float4*)Wout, (uint2*)woh,
                                          CC * CC / 4);

    dim3 gemm_grid(CC / 128, MM / 128);   // (8, 64)

    // GEMM1: x_proj = x @ Wi^T + bi
    mma_gemm<<<gemm_grid, 256, SMEM_DYN>>>(xh, wih, bi, xp);

    // Fused middle (P=4 positions per block)
    fused_mid<<<MM / 4, 256>>>(x, dw_w, dw_b, ln_g, ln_b, Wo, bo, Wm, bmv,
                               xp, samph);

    // GEMM2: out = sampled @ Wout^T + bout
    mma_gemm<<<gemm_grid, 256, SMEM_DYN>>>(samph, woh, bout, out);
}

// round 6
// speedup vs baseline: 4.9352x; 1.3710x over previous
#include <cuda_runtime.h>
#include <cuda_fp16.h>
#include <math.h>
#include <stdint.h>

// Problem constants
#define NB   4
#define LL   2048
#define CC   1024
#define KK   7
#define MM   (NB * LL)   // 8192

// Scratch (allocation-free rule: __device__ globals)
__device__ __half g_xh[MM * CC];     // fp16 x
__device__ __half g_wih[CC * CC];    // fp16 Wi
__device__ __half g_woh[CC * CC];    // fp16 Wout
__device__ float  g_xp[MM * CC];     // x_proj (fp32)
__device__ __half g_samph[MM * CC];  // sampled (fp16)

// ---------------------------------------------------------------------------
// helpers
// ---------------------------------------------------------------------------
__device__ __forceinline__ uint32_t smem_u32(const void* p) {
    uint32_t a;
    asm("{ .reg .u64 t; cvta.to.shared.u64 t, %1; cvt.u32.u64 %0, t; }"
        : "=r"(a) : "l"(p));
    return a;
}

__device__ __forceinline__ void mma_f16(float* d, const uint32_t* a,
                                        const uint32_t* b) {
    asm volatile(
        "mma.sync.aligned.m16n8k16.row.col.f32.f16.f16.f32 "
        "{%0,%1,%2,%3}, {%4,%5,%6,%7}, {%8,%9}, {%0,%1,%2,%3};"
        : "+f"(d[0]), "+f"(d[1]), "+f"(d[2]), "+f"(d[3])
        : "r"(a[0]), "r"(a[1]), "r"(a[2]), "r"(a[3]),
          "r"(b[0]), "r"(b[1]));
}

#define LDSM4(r0, r1, r2, r3, addr)                                           \
    asm volatile("ldmatrix.sync.aligned.m8n8.x4.shared.b16 {%0,%1,%2,%3}, [%4];" \
                 : "=r"(r0), "=r"(r1), "=r"(r2), "=r"(r3) : "r"(addr))

#define CP_ASYNC16(dst, src) \
    asm volatile("cp.async.cg.shared.global [%0], [%1], 16;" :: "r"(dst), "l"(src))
#define CP_COMMIT() asm volatile("cp.async.commit_group;" ::: "memory")
#define CP_WAIT1()  asm volatile("cp.async.wait_group 1;" ::: "memory")

// ---------------------------------------------------------------------------
// fp32 -> fp16 conversion pre-pass
// ---------------------------------------------------------------------------
__global__ __launch_bounds__(256)
void cvt_f16(const float4* __restrict__ in, uint2* __restrict__ out, int n4) {
    int i = blockIdx.x * blockDim.x + threadIdx.x;
    if (i < n4) {
        float4 v = in[i];
        __half2 h0 = __floats2half2_rn(v.x, v.y);
        __half2 h1 = __floats2half2_rn(v.z, v.w);
        uint2 o;
        o.x = *(uint32_t*)&h0;
        o.y = *(uint32_t*)&h1;
        out[i] = o;
    }
}

// ---------------------------------------------------------------------------
// fp16 mma.sync GEMM (NT): C[m,n] = sum_k A[m,k]*B[n,k] + bias[n]
// A,B fp16 [.,1024]; 128x128 CTA tile, BK=64 (128B rows), 8 warps (4x2),
// 32x64 warp tile, 256 threads, 3-stage cp.async, XOR swizzle, ldmatrix.
// ---------------------------------------------------------------------------
#define STAGE_BYTES 32768           // A tile 16KB + B tile 16KB
#define SMEM_DYN    (3 * STAGE_BYTES)

__device__ __forceinline__ void stage_in(uint32_t sbase,
                                         const __half* __restrict__ A,
                                         const __half* __restrict__ B,
                                         int bm, int bn, int k0, int tid) {
#pragma unroll
    for (int i = 0; i < 4; ++i) {
        int f = i * 256 + tid;            // 0..1023
        int row = f >> 3, c4 = f & 7;
        uint32_t dst = sbase + row * 128 + ((c4 ^ (row & 7)) << 4);
        const __half* src = A + (size_t)(bm + row) * 1024 + k0 + c4 * 8;
        CP_ASYNC16(dst, src);
    }
#pragma unroll
    for (int i = 0; i < 4; ++i) {
        int f = i * 256 + tid;
        int row = f >> 3, c4 = f & 7;
        uint32_t dst = sbase + 16384 + row * 128 + ((c4 ^ (row & 7)) << 4);
        const __half* src = B + (size_t)(bn + row) * 1024 + k0 + c4 * 8;
        CP_ASYNC16(dst, src);
    }
}

__global__ __launch_bounds__(256, 2)
void mma_gemm(const __half* __restrict__ A, const __half* __restrict__ B,
              const float* __restrict__ bias, float* __restrict__ Cout) {
    extern __shared__ char dyn_smem[];
    const uint32_t sb = smem_u32(dyn_smem);

    const int tid  = threadIdx.x;
    const int wid  = tid >> 5;
    const int lane = tid & 31;
    const int g    = lane >> 2;
    const int tig  = lane & 3;
    const int wm   = wid >> 1;     // 0..3  (32 rows each)
    const int wn   = wid & 1;      // 0..1  (64 cols each)
    const int bm = blockIdx.y * 128;
    const int bn = blockIdx.x * 128;

    float d[2][8][4];
#pragma unroll
    for (int i = 0; i < 2; ++i)
#pragma unroll
        for (int j = 0; j < 8; ++j)
#pragma unroll
            for (int r = 0; r < 4; ++r) d[i][j][r] = 0.f;

    // --- ldmatrix per-thread row addresses (within tile), swizzle keys ---
    // A (x4): lanes 0-15 -> k-granule lo, 16-31 -> hi; row = mbase + (lane&15)
    const int aHi = (lane >> 4) & 1;            // granule select
    uint32_t aRowOff[2];
    uint32_t aSw[2];
#pragma unroll
    for (int i = 0; i < 2; ++i) {
        int rowA = wm * 32 + i * 16 + (lane & 15);
        aRowOff[i] = (uint32_t)(rowA * 128);
        aSw[i] = (uint32_t)(rowA & 7);
    }
    // B (x4 per j-pair): mats = (j,lo),(j,hi),(j+1,lo),(j+1,hi)
    const int bHi = (lane >> 3) & 1;
    uint32_t bRowOff[4];
    uint32_t bSw[4];
#pragma unroll
    for (int j2 = 0; j2 < 4; ++j2) {
        int rowB = wn * 64 + j2 * 16 + ((lane & 16) >> 1) + (lane & 7);
        bRowOff[j2] = (uint32_t)(rowB * 128);
        bSw[j2] = (uint32_t)(rowB & 7);
    }

    // prologue
    stage_in(sb + 0 * STAGE_BYTES, A, B, bm, bn, 0, tid);
    CP_COMMIT();
    stage_in(sb + 1 * STAGE_BYTES, A, B, bm, bn, 64, tid);
    CP_COMMIT();

#pragma unroll 1
    for (int s = 0; s < 16; ++s) {
        CP_WAIT1();
        __syncthreads();

        if (s + 2 < 16)
            stage_in(sb + ((s + 2) % 3) * STAGE_BYTES, A, B, bm, bn,
                     (s + 2) * 64, tid);
        CP_COMMIT();

        const uint32_t aBase = sb + (s % 3) * STAGE_BYTES;
        const uint32_t bBase = aBase + 16384u;

#pragma unroll
        for (int ks = 0; ks < 4; ++ks) {
            const uint32_t granA = (uint32_t)(2 * ks + aHi);
            const uint32_t granB = (uint32_t)(2 * ks + bHi);

            uint32_t af[2][4];
#pragma unroll
            for (int i = 0; i < 2; ++i) {
                uint32_t addr = aBase + aRowOff[i] + ((granA ^ aSw[i]) << 4);
                LDSM4(af[i][0], af[i][1], af[i][2], af[i][3], addr);
            }
            uint32_t bf[8][2];
#pragma unroll
            for (int j2 = 0; j2 < 4; ++j2) {
                uint32_t addr = bBase + bRowOff[j2] + ((granB ^ bSw[j2]) << 4);
                LDSM4(bf[2 * j2][0], bf[2 * j2][1],
                      bf[2 * j2 + 1][0], bf[2 * j2 + 1][1], addr);
            }
#pragma unroll
            for (int i = 0; i < 2; ++i)
#pragma unroll
                for (int j = 0; j < 8; ++j)
                    mma_f16(d[i][j], af[i], bf[j]);
        }
    }

    // epilogue: D frag (i,j): rows (g, g+8), cols (2*tig, 2*tig+1)
#pragma unroll
    for (int i = 0; i < 2; ++i) {
        int row = bm + wm * 32 + i * 16 + g;
        float* o0 = Cout + (size_t)row * 1024 + bn + wn * 64;
        float* o1 = o0 + 8 * 1024;
#pragma unroll
        for (int j = 0; j < 8; ++j) {
            int col = j * 8 + tig * 2;
            float2 bb = *(const float2*)&bias[bn + wn * 64 + col];
            float2 v0, v1;
            v0.x = d[i][j][0] + bb.x;
            v0.y = d[i][j][1] + bb.y;
            v1.x = d[i][j][2] + bb.x;
            v1.y = d[i][j][3] + bb.y;
            *(float2*)(o0 + col) = v0;
            *(float2*)(o1 + col) = v1;
        }
    }
}

// ---------------------------------------------------------------------------
// Fused middle (P=1, round-4 proven version, fp16 output):
// depthwise conv(k=3,pad=1) + LayerNorm + exact GELU + heads + softmax +
// positions + 14-row gather-blend. One block (256 thr) per (n,l).
// ---------------------------------------------------------------------------
__global__ __launch_bounds__(256)
void fused_mid(const float* __restrict__ x,
               const float* __restrict__ dw_w, const float* __restrict__ dw_b,
               const float* __restrict__ ln_g, const float* __restrict__ ln_b,
               const float* __restrict__ Wo,   const float* __restrict__ bo,
               const float* __restrict__ Wm,   const float* __restrict__ bmv,
               const float* __restrict__ xp,   __half* __restrict__ sampd) {
    const int nl = blockIdx.x;           // 0..8191
    const int n = nl >> 11;
    const int l = nl & (LL - 1);
    const int tid = threadIdx.x;
    const int lane = tid & 31;
    const int wid = tid >> 5;
    const int c0 = tid * 4;

    const float* x0 = x + (size_t)nl * CC;

    // depthwise conv, k=3, zero padding at sequence boundaries
    float4 xm = *(const float4*)(x0 + c0);
    float4 xl = (l > 0)      ? *(const float4*)(x0 + c0 - CC) : make_float4(0,0,0,0);
    float4 xr = (l < LL - 1) ? *(const float4*)(x0 + c0 + CC) : make_float4(0,0,0,0);
    float4 db = *(const float4*)(dw_b + c0);
    float v[4];
    {
        const float* wp = dw_w + c0 * 3;
        v[0] = db.x + xl.x * wp[0]  + xm.x * wp[1]  + xr.x * wp[2];
        v[1] = db.y + xl.y * wp[3]  + xm.y * wp[4]  + xr.y * wp[5];
        v[2] = db.z + xl.z * wp[6]  + xm.z * wp[7]  + xr.z * wp[8];
        v[3] = db.w + xl.w * wp[9]  + xm.w * wp[10] + xr.w * wp[11];
    }

    // LayerNorm statistics (block reduce over 1024 channels)
    float s  = v[0] + v[1] + v[2] + v[3];
    float s2 = v[0]*v[0] + v[1]*v[1] + v[2]*v[2] + v[3]*v[3];
#pragma unroll
    for (int o = 16; o; o >>= 1) {
        s  += __shfl_xor_sync(0xFFFFFFFFu, s,  o);
        s2 += __shfl_xor_sync(0xFFFFFFFFu, s2, o);
    }
    __shared__ float rs[8], rs2[8];
    __shared__ float stats[2];
    if (lane == 0) { rs[wid] = s; rs2[wid] = s2; }
    __syncthreads();
    if (tid == 0) {
        float S = 0.f, S2 = 0.f;
#pragma unroll
        for (int w = 0; w < 8; ++w) { S += rs[w]; S2 += rs2[w]; }
        float mu = S * (1.f / CC);
        float var = S2 * (1.f / CC) - mu * mu;
        stats[0] = mu;
        stats[1] = rsqrtf(var + 1e-5f);
    }
    __syncthreads();
    const float mu = stats[0], rstd = stats[1];

    // LN affine + exact GELU
    float4 lg = *(const float4*)(ln_g + c0);
    float4 lb = *(const float4*)(ln_b + c0);
    float g4[4];
    {
        float h;
        h = (v[0] - mu) * rstd * lg.x + lb.x;
        g4[0] = 0.5f * h * (1.f + erff(h * 0.70710678118654752f));
        h = (v[1] - mu) * rstd * lg.y + lb.y;
        g4[1] = 0.5f * h * (1.f + erff(h * 0.70710678118654752f));
        h = (v[2] - mu) * rstd * lg.z + lb.z;
        g4[2] = 0.5f * h * (1.f + erff(h * 0.70710678118654752f));
        h = (v[3] - mu) * rstd * lg.w + lb.w;
        g4[3] = 0.5f * h * (1.f + erff(h * 0.70710678118654752f));
    }

    // offset + mask heads: 14 dot products of length 1024
    float p[14];
#pragma unroll
    for (int j = 0; j < 7; ++j) {
        float4 w1 = *(const float4*)(Wo + j * CC + c0);
        float4 w2 = *(const float4*)(Wm + j * CC + c0);
        p[j] = g4[0]*w1.x + g4[1]*w1.y + g4[2]*w1.z + g4[3]*w1.w;
        p[7+j] = g4[0]*w2.x + g4[1]*w2.y + g4[2]*w2.z + g4[3]*w2.w;
    }
#pragma unroll
    for (int o = 16; o; o >>= 1)
#pragma unroll
        for (int j = 0; j < 14; ++j)
            p[j] += __shfl_xor_sync(0xFFFFFFFFu, p[j], o);

    __shared__ float red[14][8];
    if (lane == 0)
#pragma unroll
        for (int j = 0; j < 14; ++j) red[j][wid] = p[j];
    __syncthreads();

    __shared__ int   spf[KK], spc[KK];
    __shared__ float swf[KK], swc[KK];
    if (tid == 0) {
        float ho[KK], hm[KK];
#pragma unroll
        for (int j = 0; j < KK; ++j) {
            float a = 0.f, b = 0.f;
#pragma unroll
            for (int w = 0; w < 8; ++w) { a += red[j][w]; b += red[7 + j][w]; }
            ho[j] = (a + bo[j]) * 2.0f;     // OFFSET_SCALE
            hm[j] = b + bmv[j];
        }
        // softmax over K
        float mx = hm[0];
#pragma unroll
        for (int j = 1; j < KK; ++j) mx = fmaxf(mx, hm[j]);
        float e[KK], se = 0.f;
#pragma unroll
        for (int j = 0; j < KK; ++j) { e[j] = expf(hm[j] - mx); se += e[j]; }
        float inv = 1.f / se;
#pragma unroll
        for (int k = 0; k < KK; ++k) {
            float mask = e[k] * inv;
            float ap  = (float)l + (float)(k - 3) + ho[k];
            float apc = fminf(fmaxf(ap, 0.f), (float)(LL - 1));
            int pf = (int)apc;
            if (pf > LL - 1) pf = LL - 1;
            int pc = pf + 1; if (pc > LL - 1) pc = LL - 1;
            float wc = apc - (float)pf;
            float wf = 1.f - wc;
            float valid = (ap < 0.f || ap > (float)(LL - 1)) ? 0.f : 1.f;
            spf[k] = pf; spc[k] = pc;
            swf[k] = wf * valid * mask;
            swc[k] = wc * valid * mask;
        }
    }
    __syncthreads();

    // gather-blend from x_proj (L2-resident)
    float o0 = 0.f, o1 = 0.f, o2 = 0.f, o3 = 0.f;
    const float* xpn = xp + (size_t)n * LL * CC;
#pragma unroll
    for (int k = 0; k < KK; ++k) {
        float4 rf = *(const float4*)(xpn + (size_t)spf[k] * CC + c0);
        float4 rc = *(const float4*)(xpn + (size_t)spc[k] * CC + c0);
        float wf = swf[k], wc = swc[k];
        o0 = fmaf(rf.x, wf, fmaf(rc.x, wc, o0));
        o1 = fmaf(rf.y, wf, fmaf(rc.y, wc, o1));
        o2 = fmaf(rf.z, wf, fmaf(rc.z, wc, o2));
        o3 = fmaf(rf.w, wf, fmaf(rc.w, wc, o3));
    }
    __half2 h0 = __floats2half2_rn(o0, o1);
    __half2 h1 = __floats2half2_rn(o2, o3);
    uint2 ov;
    ov.x = *(uint32_t*)&h0;
    ov.y = *(uint32_t*)&h1;
    *(uint2*)(sampd + (size_t)nl * CC + c0) = ov;
}

// ---------------------------------------------------------------------------
// Launch
// ---------------------------------------------------------------------------
extern "C" void kernel_launch(void* const* d_in, const int* in_sizes, int n_in,
                              void* d_out, int out_size) {
    const float* x    = (const float*)d_in[0];
    const float* Wi   = (const float*)d_in[1];
    const float* bi   = (const float*)d_in[2];
    const float* dw_w = (const float*)d_in[3];
    const float* dw_b = (const float*)d_in[4];
    const float* ln_g = (const float*)d_in[5];
    const float* ln_b = (const float*)d_in[6];
    const float* Wo   = (const float*)d_in[7];
    const float* bo   = (const float*)d_in[8];
    const float* Wm   = (const float*)d_in[9];
    const float* bmv  = (const float*)d_in[10];
    const float* Wout = (const float*)d_in[11];
    const float* bout = (const float*)d_in[12];
    float* out = (float*)d_out;

    __half *xh, *wih, *woh, *samph;
    float *xp;
    cudaGetSymbolAddress((void**)&xh,    g_xh);
    cudaGetSymbolAddress((void**)&wih,   g_wih);
    cudaGetSymbolAddress((void**)&woh,   g_woh);
    cudaGetSymbolAddress((void**)&xp,    g_xp);
    cudaGetSymbolAddress((void**)&samph, g_samph);

    cudaFuncSetAttribute(mma_gemm, cudaFuncAttributeMaxDynamicSharedMemorySize,
                         SMEM_DYN);

    // fp16 conversions
    cvt_f16<<<(MM * CC / 4) / 256, 256>>>((const float4*)x, (uint2*)xh,
                                          MM * CC / 4);
    cvt_f16<<<(CC * CC / 4) / 256, 256>>>((const float4*)Wi, (uint2*)wih,
                                          CC * CC / 4);
    cvt_f16<<<(CC * CC / 4) / 256, 256>>>((const float4*)Wout, (uint2*)woh,
                                          CC * CC / 4);

    dim3 gemm_grid(CC / 128, MM / 128);   // (8, 64)

    // GEMM1: x_proj = x @ Wi^T + bi
    mma_gemm<<<gemm_grid, 256, SMEM_DYN>>>(xh, wih, bi, xp);

    // Fused middle (P=1)
    fused_mid<<<MM, 256>>>(x, dw_w, dw_b, ln_g, ln_b, Wo, bo, Wm, bmv,
                           xp, samph);

    // GEMM2: out = sampled @ Wout^T + bout
    mma_gemm<<<gemm_grid, 256, SMEM_DYN>>>(samph, woh, bout, out);
}

// round 7
// speedup vs baseline: 5.0950x; 1.0324x over previous
#include <cuda_runtime.h>
#include <cuda_fp16.h>
#include <math.h>
#include <stdint.h>

// Problem constants
#define NB   4
#define LL   2048
#define CC   1024
#define KK   7
#define MM   (NB * LL)   // 8192

// Scratch (allocation-free rule: __device__ globals)
__device__ __half g_xh[MM * CC];     // fp16 x
__device__ __half g_wih[CC * CC];    // fp16 Wi
__device__ __half g_woh[CC * CC];    // fp16 Wout
__device__ __half g_xph[MM * CC];    // x_proj (fp16)
__device__ __half g_xdw[MM * CC];    // conv+LN+GELU result (fp16)
__device__ __half g_samph[MM * CC];  // sampled (fp16)
__device__ float  g_recw[MM * 16];   // per-position blend weights (wf[8], wc[8])
__device__ int    g_reci[MM * 16];   // per-position gather indices (pf[8], pc[8])

// ---------------------------------------------------------------------------
// helpers
// ---------------------------------------------------------------------------
__device__ __forceinline__ uint32_t smem_u32(const void* p) {
    uint32_t a;
    asm("{ .reg .u64 t; cvta.to.shared.u64 t, %1; cvt.u32.u64 %0, t; }"
        : "=r"(a) : "l"(p));
    return a;
}

__device__ __forceinline__ void mma_f16(float* d, const uint32_t* a,
                                        const uint32_t* b) {
    asm volatile(
        "mma.sync.aligned.m16n8k16.row.col.f32.f16.f16.f32 "
        "{%0,%1,%2,%3}, {%4,%5,%6,%7}, {%8,%9}, {%0,%1,%2,%3};"
        : "+f"(d[0]), "+f"(d[1]), "+f"(d[2]), "+f"(d[3])
        : "r"(a[0]), "r"(a[1]), "r"(a[2]), "r"(a[3]),
          "r"(b[0]), "r"(b[1]));
}

#define LDSM4(r0, r1, r2, r3, addr)                                           \
    asm volatile("ldmatrix.sync.aligned.m8n8.x4.shared.b16 {%0,%1,%2,%3}, [%4];" \
                 : "=r"(r0), "=r"(r1), "=r"(r2), "=r"(r3) : "r"(addr))

#define CP_ASYNC16(dst, src) \
    asm volatile("cp.async.cg.shared.global [%0], [%1], 16;" :: "r"(dst), "l"(src))
#define CP_COMMIT() asm volatile("cp.async.commit_group;" ::: "memory")
#define CP_WAIT1()  asm volatile("cp.async.wait_group 1;" ::: "memory")

__device__ __forceinline__ void store_out(float2 v, float* p) {
    *(float2*)p = v;
}
__device__ __forceinline__ void store_out(float2 v, __half* p) {
    *(__half2*)p = __floats2half2_rn(v.x, v.y);
}

// ---------------------------------------------------------------------------
// fp32 -> fp16 conversion pre-pass
// ---------------------------------------------------------------------------
__global__ __launch_bounds__(256)
void cvt_f16(const float4* __restrict__ in, uint2* __restrict__ out, int n4) {
    int i = blockIdx.x * blockDim.x + threadIdx.x;
    if (i < n4) {
        float4 v = in[i];
        __half2 h0 = __floats2half2_rn(v.x, v.y);
        __half2 h1 = __floats2half2_rn(v.z, v.w);
        uint2 o;
        o.x = *(uint32_t*)&h0;
        o.y = *(uint32_t*)&h1;
        out[i] = o;
    }
}

// ---------------------------------------------------------------------------
// fp16 mma.sync GEMM (NT): C[m,n] = sum_k A[m,k]*B[n,k] + bias[n]
// A,B fp16 [.,1024]; 128x128 CTA tile, BK=64 (128B rows), 8 warps (4x2),
// 32x64 warp tile, 256 threads, 3-stage cp.async, XOR swizzle, ldmatrix.
// Output type templated (fp32 or fp16).
// ---------------------------------------------------------------------------
#define STAGE_BYTES 32768           // A tile 16KB + B tile 16KB
#define SMEM_DYN    (3 * STAGE_BYTES)

__device__ __forceinline__ void stage_in(uint32_t sbase,
                                         const __half* __restrict__ A,
                                         const __half* __restrict__ B,
                                         int bm, int bn, int k0, int tid) {
#pragma unroll
    for (int i = 0; i < 4; ++i) {
        int f = i * 256 + tid;            // 0..1023
        int row = f >> 3, c4 = f & 7;
        uint32_t dst = sbase + row * 128 + ((c4 ^ (row & 7)) << 4);
        const __half* src = A + (size_t)(bm + row) * 1024 + k0 + c4 * 8;
        CP_ASYNC16(dst, src);
    }
#pragma unroll
    for (int i = 0; i < 4; ++i) {
        int f = i * 256 + tid;
        int row = f >> 3, c4 = f & 7;
        uint32_t dst = sbase + 16384 + row * 128 + ((c4 ^ (row & 7)) << 4);
        const __half* src = B + (size_t)(bn + row) * 1024 + k0 + c4 * 8;
        CP_ASYNC16(dst, src);
    }
}

template <typename OT>
__global__ __launch_bounds__(256, 2)
void mma_gemm(const __half* __restrict__ A, const __half* __restrict__ B,
              const float* __restrict__ bias, OT* __restrict__ Cout) {
    extern __shared__ char dyn_smem[];
    const uint32_t sb = smem_u32(dyn_smem);

    const int tid  = threadIdx.x;
    const int wid  = tid >> 5;
    const int lane = tid & 31;
    const int g    = lane >> 2;
    const int tig  = lane & 3;
    const int wm   = wid >> 1;     // 0..3  (32 rows each)
    const int wn   = wid & 1;      // 0..1  (64 cols each)
    const int bm = blockIdx.y * 128;
    const int bn = blockIdx.x * 128;

    float d[2][8][4];
#pragma unroll
    for (int i = 0; i < 2; ++i)
#pragma unroll
        for (int j = 0; j < 8; ++j)
#pragma unroll
            for (int r = 0; r < 4; ++r) d[i][j][r] = 0.f;

    // --- ldmatrix per-thread row addresses (within tile), swizzle keys ---
    const int aHi = (lane >> 4) & 1;
    uint32_t aRowOff[2];
    uint32_t aSw[2];
#pragma unroll
    for (int i = 0; i < 2; ++i) {
        int rowA = wm * 32 + i * 16 + (lane & 15);
        aRowOff[i] = (uint32_t)(rowA * 128);
        aSw[i] = (uint32_t)(rowA & 7);
    }
    const int bHi = (lane >> 3) & 1;
    uint32_t bRowOff[4];
    uint32_t bSw[4];
#pragma unroll
    for (int j2 = 0; j2 < 4; ++j2) {
        int rowB = wn * 64 + j2 * 16 + ((lane & 16) >> 1) + (lane & 7);
        bRowOff[j2] = (uint32_t)(rowB * 128);
        bSw[j2] = (uint32_t)(rowB & 7);
    }

    // prologue
    stage_in(sb + 0 * STAGE_BYTES, A, B, bm, bn, 0, tid);
    CP_COMMIT();
    stage_in(sb + 1 * STAGE_BYTES, A, B, bm, bn, 64, tid);
    CP_COMMIT();

#pragma unroll 1
    for (int s = 0; s < 16; ++s) {
        CP_WAIT1();
        __syncthreads();

        if (s + 2 < 16)
            stage_in(sb + ((s + 2) % 3) * STAGE_BYTES, A, B, bm, bn,
                     (s + 2) * 64, tid);
        CP_COMMIT();

        const uint32_t aBase = sb + (s % 3) * STAGE_BYTES;
        const uint32_t bBase = aBase + 16384u;

#pragma unroll
        for (int ks = 0; ks < 4; ++ks) {
            const uint32_t granA = (uint32_t)(2 * ks + aHi);
            const uint32_t granB = (uint32_t)(2 * ks + bHi);

            uint32_t af[2][4];
#pragma unroll
            for (int i = 0; i < 2; ++i) {
                uint32_t addr = aBase + aRowOff[i] + ((granA ^ aSw[i]) << 4);
                LDSM4(af[i][0], af[i][1], af[i][2], af[i][3], addr);
            }
            uint32_t bf[8][2];
#pragma unroll
            for (int j2 = 0; j2 < 4; ++j2) {
                uint32_t addr = bBase + bRowOff[j2] + ((granB ^ bSw[j2]) << 4);
                LDSM4(bf[2 * j2][0], bf[2 * j2][1],
                      bf[2 * j2 + 1][0], bf[2 * j2 + 1][1], addr);
            }
#pragma unroll
            for (int i = 0; i < 2; ++i)
#pragma unroll
                for (int j = 0; j < 8; ++j)
                    mma_f16(d[i][j], af[i], bf[j]);
        }
    }

    // epilogue: D frag (i,j): rows (g, g+8), cols (2*tig, 2*tig+1)
#pragma unroll
    for (int i = 0; i < 2; ++i) {
        int row = bm + wm * 32 + i * 16 + g;
        OT* o0 = Cout + (size_t)row * 1024 + bn + wn * 64;
        OT* o1 = o0 + 8 * 1024;
#pragma unroll
        for (int j = 0; j < 8; ++j) {
            int col = j * 8 + tig * 2;
            float2 bb = *(const float2*)&bias[bn + wn * 64 + col];
            float2 v0, v1;
            v0.x = d[i][j][0] + bb.x;
            v0.y = d[i][j][1] + bb.y;
            v1.x = d[i][j][2] + bb.x;
            v1.y = d[i][j][3] + bb.y;
            store_out(v0, o0 + col);
            store_out(v1, o1 + col);
        }
    }
}

// ---------------------------------------------------------------------------
// Kernel A: depthwise conv(k=3,pad=1) + LayerNorm + exact GELU -> x_dw fp16
// One block (256 thr) per (n,l); 4 channels per thread.
// ---------------------------------------------------------------------------
__global__ __launch_bounds__(256)
void conv_ln_gelu(const float* __restrict__ x,
                  const float* __restrict__ dw_w, const float* __restrict__ dw_b,
                  const float* __restrict__ ln_g, const float* __restrict__ ln_b,
                  __half* __restrict__ xdw) {
    const int nl = blockIdx.x;           // 0..8191
    const int l = nl & (LL - 1);
    const int tid = threadIdx.x;
    const int lane = tid & 31;
    const int wid = tid >> 5;
    const int c0 = tid * 4;

    const float* x0 = x + (size_t)nl * CC;

    float4 xm = *(const float4*)(x0 + c0);
    float4 xl = (l > 0)      ? *(const float4*)(x0 + c0 - CC) : make_float4(0,0,0,0);
    float4 xr = (l < LL - 1) ? *(const float4*)(x0 + c0 + CC) : make_float4(0,0,0,0);
    float4 db = *(const float4*)(dw_b + c0);
    float v[4];
    {
        const float* wp = dw_w + c0 * 3;
        v[0] = db.x + xl.x * wp[0]  + xm.x * wp[1]  + xr.x * wp[2];
        v[1] = db.y + xl.y * wp[3]  + xm.y * wp[4]  + xr.y * wp[5];
        v[2] = db.z + xl.z * wp[6]  + xm.z * wp[7]  + xr.z * wp[8];
        v[3] = db.w + xl.w * wp[9]  + xm.w * wp[10] + xr.w * wp[11];
    }

    float s  = v[0] + v[1] + v[2] + v[3];
    float s2 = v[0]*v[0] + v[1]*v[1] + v[2]*v[2] + v[3]*v[3];
#pragma unroll
    for (int o = 16; o; o >>= 1) {
        s  += __shfl_xor_sync(0xFFFFFFFFu, s,  o);
        s2 += __shfl_xor_sync(0xFFFFFFFFu, s2, o);
    }
    __shared__ float rs[8], rs2[8];
    __shared__ float stats[2];
    if (lane == 0) { rs[wid] = s; rs2[wid] = s2; }
    __syncthreads();
    if (tid == 0) {
        float S = 0.f, S2 = 0.f;
#pragma unroll
        for (int w = 0; w < 8; ++w) { S += rs[w]; S2 += rs2[w]; }
        float mu = S * (1.f / CC);
        float var = S2 * (1.f / CC) - mu * mu;
        stats[0] = mu;
        stats[1] = rsqrtf(var + 1e-5f);
    }
    __syncthreads();
    const float mu = stats[0], rstd = stats[1];

    float4 lg = *(const float4*)(ln_g + c0);
    float4 lb = *(const float4*)(ln_b + c0);
    float g0, g1, g2, g3, h;
    h = (v[0] - mu) * rstd * lg.x + lb.x;
    g0 = 0.5f * h * (1.f + erff(h * 0.70710678118654752f));
    h = (v[1] - mu) * rstd * lg.y + lb.y;
    g1 = 0.5f * h * (1.f + erff(h * 0.70710678118654752f));
    h = (v[2] - mu) * rstd * lg.z + lb.z;
    g2 = 0.5f * h * (1.f + erff(h * 0.70710678118654752f));
    h = (v[3] - mu) * rstd * lg.w + lb.w;
    g3 = 0.5f * h * (1.f + erff(h * 0.70710678118654752f));

    __half2 h0 = __floats2half2_rn(g0, g1);
    __half2 h1 = __floats2half2_rn(g2, g3);
    uint2 ov;
    ov.x = *(uint32_t*)&h0;
    ov.y = *(uint32_t*)&h1;
    *(uint2*)(xdw + (size_t)nl * CC + c0) = ov;
}

// ---------------------------------------------------------------------------
// Kernel B: offset/mask heads + softmax + positions -> gather records.
// Warp per position, 8 positions per block, no __syncthreads.
// ---------------------------------------------------------------------------
__global__ __launch_bounds__(256)
void heads_pos(const __half* __restrict__ xdw,
               const float* __restrict__ Wo, const float* __restrict__ bo,
               const float* __restrict__ Wm, const float* __restrict__ bmv,
               float* __restrict__ recw, int* __restrict__ reci) {
    const int wid  = threadIdx.x >> 5;
    const int lane = threadIdx.x & 31;
    const int pos  = blockIdx.x * 8 + wid;
    const int l    = pos & (LL - 1);

    const __half2* xr = (const __half2*)(xdw + (size_t)pos * CC);

    float p[14];
#pragma unroll
    for (int j = 0; j < 14; ++j) p[j] = 0.f;

#pragma unroll
    for (int i = 0; i < 16; ++i) {
        __half2 hv = xr[lane + 32 * i];
        float2 f = __half22float2(hv);
        int c = 2 * (lane + 32 * i);
#pragma unroll
        for (int j = 0; j < 7; ++j) {
            float2 w1 = *(const float2*)(Wo + j * CC + c);
            float2 w2 = *(const float2*)(Wm + j * CC + c);
            p[j]     = fmaf(f.x, w1.x, fmaf(f.y, w1.y, p[j]));
            p[7 + j] = fmaf(f.x, w2.x, fmaf(f.y, w2.y, p[7 + j]));
        }
    }
#pragma unroll
    for (int o = 16; o; o >>= 1)
#pragma unroll
        for (int j = 0; j < 14; ++j)
            p[j] += __shfl_xor_sync(0xFFFFFFFFu, p[j], o);

    if (lane == 0) {
        float ho[KK], hm[KK];
#pragma unroll
        for (int j = 0; j < KK; ++j) {
            ho[j] = (p[j] + bo[j]) * 2.0f;     // OFFSET_SCALE
            hm[j] = p[7 + j] + bmv[j];
        }
        float mx = hm[0];
#pragma unroll
        for (int j = 1; j < KK; ++j) mx = fmaxf(mx, hm[j]);
        float e[KK], se = 0.f;
#pragma unroll
        for (int j = 0; j < KK; ++j) { e[j] = expf(hm[j] - mx); se += e[j]; }
        float inv = 1.f / se;

        float* rw = recw + (size_t)pos * 16;
        int*   ri = reci + (size_t)pos * 16;
#pragma unroll
        for (int k = 0; k < KK; ++k) {
            float mask = e[k] * inv;
            float ap  = (float)l + (float)(k - 3) + ho[k];
            float apc = fminf(fmaxf(ap, 0.f), (float)(LL - 1));
            int pf = (int)apc;
            if (pf > LL - 1) pf = LL - 1;
            int pc = pf + 1; if (pc > LL - 1) pc = LL - 1;
            float wc = apc - (float)pf;
            float wf = 1.f - wc;
            float valid = (ap < 0.f || ap > (float)(LL - 1)) ? 0.f : 1.f;
            rw[k]     = wf * valid * mask;
            rw[8 + k] = wc * valid * mask;
            ri[k]     = pf;
            ri[8 + k] = pc;
        }
    }
}

// ---------------------------------------------------------------------------
// Kernel C: gather-blend from fp16 x_proj -> sampled fp16.
// One block (128 thr) per position, 8 channels per thread, no __syncthreads.
// ---------------------------------------------------------------------------
__global__ __launch_bounds__(128)
void gather_blend(const __half* __restrict__ xph,
                  const float* __restrict__ recw, const int* __restrict__ reci,
                  __half* __restrict__ samp) {
    const int nl = blockIdx.x;
    const int n  = nl >> 11;
    const int c0 = threadIdx.x * 8;

    const float* rw = recw + (size_t)nl * 16;
    const int*   ri = reci + (size_t)nl * 16;

    float wf[KK], wc[KK];
    int   pf[KK], pc[KK];
#pragma unroll
    for (int k = 0; k < KK; ++k) {
        wf[k] = __ldg(rw + k);
        wc[k] = __ldg(rw + 8 + k);
        pf[k] = __ldg(ri + k);
        pc[k] = __ldg(ri + 8 + k);
    }

    const __half* xpn = xph + (size_t)n * LL * CC + c0;

    float acc[8];
#pragma unroll
    for (int m = 0; m < 8; ++m) acc[m] = 0.f;

#pragma unroll
    for (int k = 0; k < KK; ++k) {
        uint4 rf = *(const uint4*)(xpn + (size_t)pf[k] * CC);
        uint4 rc = *(const uint4*)(xpn + (size_t)pc[k] * CC);
        float w0 = wf[k], w1 = wc[k];
        const __half2* hf = (const __half2*)&rf;
        const __half2* hc = (const __half2*)&rc;
#pragma unroll
        for (int m = 0; m < 4; ++m) {
            float2 ff = __half22float2(hf[m]);
            float2 fc = __half22float2(hc[m]);
            acc[2*m + 0] = fmaf(ff.x, w0, fmaf(fc.x, w1, acc[2*m + 0]));
            acc[2*m + 1] = fmaf(ff.y, w0, fmaf(fc.y, w1, acc[2*m + 1]));
        }
    }

    uint4 ov;
    __half2 o0 = __floats2half2_rn(acc[0], acc[1]);
    __half2 o1 = __floats2half2_rn(acc[2], acc[3]);
    __half2 o2 = __floats2half2_rn(acc[4], acc[5]);
    __half2 o3 = __floats2half2_rn(acc[6], acc[7]);
    ov.x = *(uint32_t*)&o0; ov.y = *(uint32_t*)&o1;
    ov.z = *(uint32_t*)&o2; ov.w = *(uint32_t*)&o3;
    *(uint4*)(samp + (size_t)nl * CC + c0) = ov;
}

// ---------------------------------------------------------------------------
// Launch
// ---------------------------------------------------------------------------
extern "C" void kernel_launch(void* const* d_in, const int* in_sizes, int n_in,
                              void* d_out, int out_size) {
    const float* x    = (const float*)d_in[0];
    const float* Wi   = (const float*)d_in[1];
    const float* bi   = (const float*)d_in[2];
    const float* dw_w = (const float*)d_in[3];
    const float* dw_b = (const float*)d_in[4];
    const float* ln_g = (const float*)d_in[5];
    const float* ln_b = (const float*)d_in[6];
    const float* Wo   = (const float*)d_in[7];
    const float* bo   = (const float*)d_in[8];
    const float* Wm   = (const float*)d_in[9];
    const float* bmv  = (const float*)d_in[10];
    const float* Wout = (const float*)d_in[11];
    const float* bout = (const float*)d_in[12];
    float* out = (float*)d_out;

    __half *xh, *wih, *woh, *xph, *xdw, *samph;
    float *recw;
    int *reci;
    cudaGetSymbolAddress((void**)&xh,    g_xh);
    cudaGetSymbolAddress((void**)&wih,   g_wih);
    cudaGetSymbolAddress((void**)&woh,   g_woh);
    cudaGetSymbolAddress((void**)&xph,   g_xph);
    cudaGetSymbolAddress((void**)&xdw,   g_xdw);
    cudaGetSymbolAddress((void**)&samph, g_samph);
    cudaGetSymbolAddress((void**)&recw,  g_recw);
    cudaGetSymbolAddress((void**)&reci,  g_reci);

    cudaFuncSetAttribute(mma_gemm<__half>,
                         cudaFuncAttributeMaxDynamicSharedMemorySize, SMEM_DYN);
    cudaFuncSetAttribute(mma_gemm<float>,
                         cudaFuncAttributeMaxDynamicSharedMemorySize, SMEM_DYN);

    // fp16 conversions
    cvt_f16<<<(MM * CC / 4) / 256, 256>>>((const float4*)x, (uint2*)xh,
                                          MM * CC / 4);
    cvt_f16<<<(CC * CC / 4) / 256, 256>>>((const float4*)Wi, (uint2*)wih,
                                          CC * CC / 4);
    cvt_f16<<<(CC * CC / 4) / 256, 256>>>((const float4*)Wout, (uint2*)woh,
                                          CC * CC / 4);

    dim3 gemm_grid(CC / 128, MM / 128);   // (8, 64)

    // GEMM1: x_proj = x @ Wi^T + bi  (fp16 output)
    mma_gemm<__half><<<gemm_grid, 256, SMEM_DYN>>>(xh, wih, bi, xph);

    // A: conv + LN + GELU -> xdw (fp16)
    conv_ln_gelu<<<MM, 256>>>(x, dw_w, dw_b, ln_g, ln_b, xdw);

    // B: heads + softmax + positions -> records
    heads_pos<<<MM / 8, 256>>>(xdw, Wo, bo, Wm, bmv, recw, reci);

    // C: gather-blend -> sampled (fp16)
    gather_blend<<<MM, 128>>>(xph, recw, reci, samph);

    // GEMM2: out = sampled @ Wout^T + bout (fp32 output)
    mma_gemm<float><<<gemm_grid, 256, SMEM_DYN>>>(samph, woh, bout, out);
}

// round 8
// speedup vs baseline: 5.4613x; 1.0719x over previous
#include <cuda_runtime.h>
#include <cuda_fp16.h>
#include <math.h>
#include <stdint.h>

// Problem constants
#define NB   4
#define LL   2048
#define CC   1024
#define KK   7
#define MM   (NB * LL)   // 8192

// Scratch (allocation-free rule: __device__ globals)
__device__ __half g_xh[MM * CC];     // fp16 x
__device__ __half g_wih[CC * CC];    // fp16 Wi
__device__ __half g_woh[CC * CC];    // fp16 Wout
__device__ __half g_xph[MM * CC];    // x_proj (fp16)
__device__ __half g_xdw[MM * CC];    // conv+LN+GELU result (fp16)
__device__ __half g_samph[MM * CC];  // sampled (fp16)
__device__ float  g_recw[MM * 16];   // per-position blend weights (wf[8], wc[8])
__device__ int    g_reci[MM * 16];   // per-position gather indices (pf[8], pc[8])

// ---------------------------------------------------------------------------
// helpers
// ---------------------------------------------------------------------------
__device__ __forceinline__ uint32_t smem_u32(const void* p) {
    uint32_t a;
    asm("{ .reg .u64 t; cvta.to.shared.u64 t, %1; cvt.u32.u64 %0, t; }"
        : "=r"(a) : "l"(p));
    return a;
}

__device__ __forceinline__ void mma_f16(float* d, const uint32_t* a,
                                        const uint32_t* b) {
    asm volatile(
        "mma.sync.aligned.m16n8k16.row.col.f32.f16.f16.f32 "
        "{%0,%1,%2,%3}, {%4,%5,%6,%7}, {%8,%9}, {%0,%1,%2,%3};"
        : "+f"(d[0]), "+f"(d[1]), "+f"(d[2]), "+f"(d[3])
        : "r"(a[0]), "r"(a[1]), "r"(a[2]), "r"(a[3]),
          "r"(b[0]), "r"(b[1]));
}

#define LDSM4(r0, r1, r2, r3, addr)                                           \
    asm volatile("ldmatrix.sync.aligned.m8n8.x4.shared.b16 {%0,%1,%2,%3}, [%4];" \
                 : "=r"(r0), "=r"(r1), "=r"(r2), "=r"(r3) : "r"(addr))

#define CP_ASYNC16(dst, src) \
    asm volatile("cp.async.cg.shared.global [%0], [%1], 16;" :: "r"(dst), "l"(src))
#define CP_COMMIT() asm volatile("cp.async.commit_group;" ::: "memory")
#define CP_WAIT1()  asm volatile("cp.async.wait_group 1;" ::: "memory")

__device__ __forceinline__ void store_out(float2 v, float* p) {
    *(float2*)p = v;
}
__device__ __forceinline__ void store_out(float2 v, __half* p) {
    *(__half2*)p = __floats2half2_rn(v.x, v.y);
}

// ---------------------------------------------------------------------------
// fp32 -> fp16 conversion pre-pass
// ---------------------------------------------------------------------------
__global__ __launch_bounds__(256)
void cvt_f16(const float4* __restrict__ in, uint2* __restrict__ out, int n4) {
    int i = blockIdx.x * blockDim.x + threadIdx.x;
    if (i < n4) {
        float4 v = in[i];
        __half2 h0 = __floats2half2_rn(v.x, v.y);
        __half2 h1 = __floats2half2_rn(v.z, v.w);
        uint2 o;
        o.x = *(uint32_t*)&h0;
        o.y = *(uint32_t*)&h1;
        out[i] = o;
    }
}

// ---------------------------------------------------------------------------
// fp16 mma.sync GEMM (NT): C[m,n] = sum_k A[m,k]*B[n,k] + bias[n]
// A,B fp16 [.,1024]; 128x128 CTA tile, BK=64 (128B rows), 8 warps (4x2),
// 32x64 warp tile, 256 threads, 3-stage cp.async, XOR swizzle, ldmatrix.
// Output type templated (fp32 or fp16).
// ---------------------------------------------------------------------------
#define STAGE_BYTES 32768           // A tile 16KB + B tile 16KB
#define SMEM_DYN    (3 * STAGE_BYTES)

__device__ __forceinline__ void stage_in(uint32_t sbase,
                                         const __half* __restrict__ A,
                                         const __half* __restrict__ B,
                                         int bm, int bn, int k0, int tid) {
#pragma unroll
    for (int i = 0; i < 4; ++i) {
        int f = i * 256 + tid;            // 0..1023
        int row = f >> 3, c4 = f & 7;
        uint32_t dst = sbase + row * 128 + ((c4 ^ (row & 7)) << 4);
        const __half* src = A + (size_t)(bm + row) * 1024 + k0 + c4 * 8;
        CP_ASYNC16(dst, src);
    }
#pragma unroll
    for (int i = 0; i < 4; ++i) {
        int f = i * 256 + tid;
        int row = f >> 3, c4 = f & 7;
        uint32_t dst = sbase + 16384 + row * 128 + ((c4 ^ (row & 7)) << 4);
        const __half* src = B + (size_t)(bn + row) * 1024 + k0 + c4 * 8;
        CP_ASYNC16(dst, src);
    }
}

template <typename OT>
__global__ __launch_bounds__(256, 2)
void mma_gemm(const __half* __restrict__ A, const __half* __restrict__ B,
              const float* __restrict__ bias, OT* __restrict__ Cout) {
    extern __shared__ char dyn_smem[];
    const uint32_t sb = smem_u32(dyn_smem);

    const int tid  = threadIdx.x;
    const int wid  = tid >> 5;
    const int lane = tid & 31;
    const int g    = lane >> 2;
    const int tig  = lane & 3;
    const int wm   = wid >> 1;     // 0..3  (32 rows each)
    const int wn   = wid & 1;      // 0..1  (64 cols each)
    const int bm = blockIdx.y * 128;
    const int bn = blockIdx.x * 128;

    float d[2][8][4];
#pragma unroll
    for (int i = 0; i < 2; ++i)
#pragma unroll
        for (int j = 0; j < 8; ++j)
#pragma unroll
            for (int r = 0; r < 4; ++r) d[i][j][r] = 0.f;

    // --- ldmatrix per-thread row addresses (within tile), swizzle keys ---
    const int aHi = (lane >> 4) & 1;
    uint32_t aRowOff[2];
    uint32_t aSw[2];
#pragma unroll
    for (int i = 0; i < 2; ++i) {
        int rowA = wm * 32 + i * 16 + (lane & 15);
        aRowOff[i] = (uint32_t)(rowA * 128);
        aSw[i] = (uint32_t)(rowA & 7);
    }
    const int bHi = (lane >> 3) & 1;
    uint32_t bRowOff[4];
    uint32_t bSw[4];
#pragma unroll
    for (int j2 = 0; j2 < 4; ++j2) {
        int rowB = wn * 64 + j2 * 16 + ((lane & 16) >> 1) + (lane & 7);
        bRowOff[j2] = (uint32_t)(rowB * 128);
        bSw[j2] = (uint32_t)(rowB & 7);
    }

    // prologue
    stage_in(sb + 0 * STAGE_BYTES, A, B, bm, bn, 0, tid);
    CP_COMMIT();
    stage_in(sb + 1 * STAGE_BYTES, A, B, bm, bn, 64, tid);
    CP_COMMIT();

#pragma unroll 1
    for (int s = 0; s < 16; ++s) {
        CP_WAIT1();
        __syncthreads();

        if (s + 2 < 16)
            stage_in(sb + ((s + 2) % 3) * STAGE_BYTES, A, B, bm, bn,
                     (s + 2) * 64, tid);
        CP_COMMIT();

        const uint32_t aBase = sb + (s % 3) * STAGE_BYTES;
        const uint32_t bBase = aBase + 16384u;

#pragma unroll
        for (int ks = 0; ks < 4; ++ks) {
            const uint32_t granA = (uint32_t)(2 * ks + aHi);
            const uint32_t granB = (uint32_t)(2 * ks + bHi);

            uint32_t af[2][4];
#pragma unroll
            for (int i = 0; i < 2; ++i) {
                uint32_t addr = aBase + aRowOff[i] + ((granA ^ aSw[i]) << 4);
                LDSM4(af[i][0], af[i][1], af[i][2], af[i][3], addr);
            }
            uint32_t bf[8][2];
#pragma unroll
            for (int j2 = 0; j2 < 4; ++j2) {
                uint32_t addr = bBase + bRowOff[j2] + ((granB ^ bSw[j2]) << 4);
                LDSM4(bf[2 * j2][0], bf[2 * j2][1],
                      bf[2 * j2 + 1][0], bf[2 * j2 + 1][1], addr);
            }
#pragma unroll
            for (int i = 0; i < 2; ++i)
#pragma unroll
                for (int j = 0; j < 8; ++j)
                    mma_f16(d[i][j], af[i], bf[j]);
        }
    }

    // epilogue: D frag (i,j): rows (g, g+8), cols (2*tig, 2*tig+1)
#pragma unroll
    for (int i = 0; i < 2; ++i) {
        int row = bm + wm * 32 + i * 16 + g;
        OT* o0 = Cout + (size_t)row * 1024 + bn + wn * 64;
        OT* o1 = o0 + 8 * 1024;
#pragma unroll
        for (int j = 0; j < 8; ++j) {
            int col = j * 8 + tig * 2;
            float2 bb = *(const float2*)&bias[bn + wn * 64 + col];
            float2 v0, v1;
            v0.x = d[i][j][0] + bb.x;
            v0.y = d[i][j][1] + bb.y;
            v1.x = d[i][j][2] + bb.x;
            v1.y = d[i][j][3] + bb.y;
            store_out(v0, o0 + col);
            store_out(v1, o1 + col);
        }
    }
}

// ---------------------------------------------------------------------------
// Kernel A: depthwise conv(k=3,pad=1) + LayerNorm + exact GELU -> x_dw fp16
// One block (256 thr) per (n,l); 4 channels per thread.
// ---------------------------------------------------------------------------
__global__ __launch_bounds__(256)
void conv_ln_gelu(const float* __restrict__ x,
                  const float* __restrict__ dw_w, const float* __restrict__ dw_b,
                  const float* __restrict__ ln_g, const float* __restrict__ ln_b,
                  __half* __restrict__ xdw) {
    const int nl = blockIdx.x;           // 0..8191
    const int l = nl & (LL - 1);
    const int tid = threadIdx.x;
    const int lane = tid & 31;
    const int wid = tid >> 5;
    const int c0 = tid * 4;

    const float* x0 = x + (size_t)nl * CC;

    float4 xm = *(const float4*)(x0 + c0);
    float4 xl = (l > 0)      ? *(const float4*)(x0 + c0 - CC) : make_float4(0,0,0,0);
    float4 xr = (l < LL - 1) ? *(const float4*)(x0 + c0 + CC) : make_float4(0,0,0,0);
    float4 db = *(const float4*)(dw_b + c0);
    float v[4];
    {
        const float* wp = dw_w + c0 * 3;
        v[0] = db.x + xl.x * wp[0]  + xm.x * wp[1]  + xr.x * wp[2];
        v[1] = db.y + xl.y * wp[3]  + xm.y * wp[4]  + xr.y * wp[5];
        v[2] = db.z + xl.z * wp[6]  + xm.z * wp[7]  + xr.z * wp[8];
        v[3] = db.w + xl.w * wp[9]  + xm.w * wp[10] + xr.w * wp[11];
    }

    float s  = v[0] + v[1] + v[2] + v[3];
    float s2 = v[0]*v[0] + v[1]*v[1] + v[2]*v[2] + v[3]*v[3];
#pragma unroll
    for (int o = 16; o; o >>= 1) {
        s  += __shfl_xor_sync(0xFFFFFFFFu, s,  o);
        s2 += __shfl_xor_sync(0xFFFFFFFFu, s2, o);
    }
    __shared__ float rs[8], rs2[8];
    __shared__ float stats[2];
    if (lane == 0) { rs[wid] = s; rs2[wid] = s2; }
    __syncthreads();
    if (tid == 0) {
        float S = 0.f, S2 = 0.f;
#pragma unroll
        for (int w = 0; w < 8; ++w) { S += rs[w]; S2 += rs2[w]; }
        float mu = S * (1.f / CC);
        float var = S2 * (1.f / CC) - mu * mu;
        stats[0] = mu;
        stats[1] = rsqrtf(var + 1e-5f);
    }
    __syncthreads();
    const float mu = stats[0], rstd = stats[1];

    float4 lg = *(const float4*)(ln_g + c0);
    float4 lb = *(const float4*)(ln_b + c0);
    float g0, g1, g2, g3, h;
    h = (v[0] - mu) * rstd * lg.x + lb.x;
    g0 = 0.5f * h * (1.f + erff(h * 0.70710678118654752f));
    h = (v[1] - mu) * rstd * lg.y + lb.y;
    g1 = 0.5f * h * (1.f + erff(h * 0.70710678118654752f));
    h = (v[2] - mu) * rstd * lg.z + lb.z;
    g2 = 0.5f * h * (1.f + erff(h * 0.70710678118654752f));
    h = (v[3] - mu) * rstd * lg.w + lb.w;
    g3 = 0.5f * h * (1.f + erff(h * 0.70710678118654752f));

    __half2 h0 = __floats2half2_rn(g0, g1);
    __half2 h1 = __floats2half2_rn(g2, g3);
    uint2 ov;
    ov.x = *(uint32_t*)&h0;
    ov.y = *(uint32_t*)&h1;
    *(uint2*)(xdw + (size_t)nl * CC + c0) = ov;
}

// ---------------------------------------------------------------------------
// Kernel B: offset/mask heads + softmax + positions -> gather records.
// Warp per position, 8 positions per block, no __syncthreads.
// ---------------------------------------------------------------------------
__global__ __launch_bounds__(256)
void heads_pos(const __half* __restrict__ xdw,
               const float* __restrict__ Wo, const float* __restrict__ bo,
               const float* __restrict__ Wm, const float* __restrict__ bmv,
               float* __restrict__ recw, int* __restrict__ reci) {
    const int wid  = threadIdx.x >> 5;
    const int lane = threadIdx.x & 31;
    const int pos  = blockIdx.x * 8 + wid;
    const int l    = pos & (LL - 1);

    const __half2* xr = (const __half2*)(xdw + (size_t)pos * CC);

    float p[14];
#pragma unroll
    for (int j = 0; j < 14; ++j) p[j] = 0.f;

#pragma unroll
    for (int i = 0; i < 16; ++i) {
        __half2 hv = xr[lane + 32 * i];
        float2 f = __half22float2(hv);
        int c = 2 * (lane + 32 * i);
#pragma unroll
        for (int j = 0; j < 7; ++j) {
            float2 w1 = *(const float2*)(Wo + j * CC + c);
            float2 w2 = *(const float2*)(Wm + j * CC + c);
            p[j]     = fmaf(f.x, w1.x, fmaf(f.y, w1.y, p[j]));
            p[7 + j] = fmaf(f.x, w2.x, fmaf(f.y, w2.y, p[7 + j]));
        }
    }
#pragma unroll
    for (int o = 16; o; o >>= 1)
#pragma unroll
        for (int j = 0; j < 14; ++j)
            p[j] += __shfl_xor_sync(0xFFFFFFFFu, p[j], o);

    if (lane == 0) {
        float ho[KK], hm[KK];
#pragma unroll
        for (int j = 0; j < KK; ++j) {
            ho[j] = (p[j] + bo[j]) * 2.0f;     // OFFSET_SCALE
            hm[j] = p[7 + j] + bmv[j];
        }
        float mx = hm[0];
#pragma unroll
        for (int j = 1; j < KK; ++j) mx = fmaxf(mx, hm[j]);
        float e[KK], se = 0.f;
#pragma unroll
        for (int j = 0; j < KK; ++j) { e[j] = expf(hm[j] - mx); se += e[j]; }
        float inv = 1.f / se;

        float* rw = recw + (size_t)pos * 16;
        int*   ri = reci + (size_t)pos * 16;
#pragma unroll
        for (int k = 0; k < KK; ++k) {
            float mask = e[k] * inv;
            float ap  = (float)l + (float)(k - 3) + ho[k];
            float apc = fminf(fmaxf(ap, 0.f), (float)(LL - 1));
            int pf = (int)apc;
            if (pf > LL - 1) pf = LL - 1;
            int pc = pf + 1; if (pc > LL - 1) pc = LL - 1;
            float wc = apc - (float)pf;
            float wf = 1.f - wc;
            float valid = (ap < 0.f || ap > (float)(LL - 1)) ? 0.f : 1.f;
            rw[k]     = wf * valid * mask;
            rw[8 + k] = wc * valid * mask;
            ri[k]     = pf;
            ri[8 + k] = pc;
        }
    }
}

// ---------------------------------------------------------------------------
// Kernel C: gather-blend from fp16 x_proj -> sampled fp16.
// One block (128 thr) per position, 8 channels per thread, no __syncthreads.
// ---------------------------------------------------------------------------
__global__ __launch_bounds__(128)
void gather_blend(const __half* __restrict__ xph,
                  const float* __restrict__ recw, const int* __restrict__ reci,
                  __half* __restrict__ samp) {
    const int nl = blockIdx.x;
    const int n  = nl >> 11;
    const int c0 = threadIdx.x * 8;

    const float* rw = recw + (size_t)nl * 16;
    const int*   ri = reci + (size_t)nl * 16;

    float wf[KK], wc[KK];
    int   pf[KK], pc[KK];
#pragma unroll
    for (int k = 0; k < KK; ++k) {
        wf[k] = __ldg(rw + k);
        wc[k] = __ldg(rw + 8 + k);
        pf[k] = __ldg(ri + k);
        pc[k] = __ldg(ri + 8 + k);
    }

    const __half* xpn = xph + (size_t)n * LL * CC + c0;

    float acc[8];
#pragma unroll
    for (int m = 0; m < 8; ++m) acc[m] = 0.f;

#pragma unroll
    for (int k = 0; k < KK; ++k) {
        uint4 rf = *(const uint4*)(xpn + (size_t)pf[k] * CC);
        uint4 rc = *(const uint4*)(xpn + (size_t)pc[k] * CC);
        float w0 = wf[k], w1 = wc[k];
        const __half2* hf = (const __half2*)&rf;
        const __half2* hc = (const __half2*)&rc;
#pragma unroll
        for (int m = 0; m < 4; ++m) {
            float2 ff = __half22float2(hf[m]);
            float2 fc = __half22float2(hc[m]);
            acc[2*m + 0] = fmaf(ff.x, w0, fmaf(fc.x, w1, acc[2*m + 0]));
            acc[2*m + 1] = fmaf(ff.y, w0, fmaf(fc.y, w1, acc[2*m + 1]));
        }
    }

    uint4 ov;
    __half2 o0 = __floats2half2_rn(acc[0], acc[1]);
    __half2 o1 = __floats2half2_rn(acc[2], acc[3]);
    __half2 o2 = __floats2half2_rn(acc[4], acc[5]);
    __half2 o3 = __floats2half2_rn(acc[6], acc[7]);
    ov.x = *(uint32_t*)&o0; ov.y = *(uint32_t*)&o1;
    ov.z = *(uint32_t*)&o2; ov.w = *(uint32_t*)&o3;
    *(uint4*)(samp + (size_t)nl * CC + c0) = ov;
}

// ---------------------------------------------------------------------------
// Launch — fork/join: GEMM1 (tensor-bound) overlaps conv/heads (memory-bound).
//
//   main:  cvt_x -> cvt_wi -> GEMM1 ----------------\
//                                                    join -> C -> GEMM2
//   side:  (fork) conv_ln_gelu -> heads_pos -> cvt_wo/
//
// Streams/events are created once (host-side resources, not device memory);
// the launched work is identical on every call.
// ---------------------------------------------------------------------------
extern "C" void kernel_launch(void* const* d_in, const int* in_sizes, int n_in,
                              void* d_out, int out_size) {
    const float* x    = (const float*)d_in[0];
    const float* Wi   = (const float*)d_in[1];
    const float* bi   = (const float*)d_in[2];
    const float* dw_w = (const float*)d_in[3];
    const float* dw_b = (const float*)d_in[4];
    const float* ln_g = (const float*)d_in[5];
    const float* ln_b = (const float*)d_in[6];
    const float* Wo   = (const float*)d_in[7];
    const float* bo   = (const float*)d_in[8];
    const float* Wm   = (const float*)d_in[9];
    const float* bmv  = (const float*)d_in[10];
    const float* Wout = (const float*)d_in[11];
    const float* bout = (const float*)d_in[12];
    float* out = (float*)d_out;

    __half *xh, *wih, *woh, *xph, *xdw, *samph;
    float *recw;
    int *reci;
    cudaGetSymbolAddress((void**)&xh,    g_xh);
    cudaGetSymbolAddress((void**)&wih,   g_wih);
    cudaGetSymbolAddress((void**)&woh,   g_woh);
    cudaGetSymbolAddress((void**)&xph,   g_xph);
    cudaGetSymbolAddress((void**)&xdw,   g_xdw);
    cudaGetSymbolAddress((void**)&samph, g_samph);
    cudaGetSymbolAddress((void**)&recw,  g_recw);
    cudaGetSymbolAddress((void**)&reci,  g_reci);

    cudaFuncSetAttribute(mma_gemm<__half>,
                         cudaFuncAttributeMaxDynamicSharedMemorySize, SMEM_DYN);
    cudaFuncSetAttribute(mma_gemm<float>,
                         cudaFuncAttributeMaxDynamicSharedMemorySize, SMEM_DYN);

    // One-time host-side stream/event creation (no device memory involved).
    static cudaStream_t s_side = nullptr;
    static cudaEvent_t  ev_fork = nullptr, ev_side_done = nullptr;
    if (s_side == nullptr) {
        cudaStreamCreateWithFlags(&s_side, cudaStreamNonBlocking);
        cudaEventCreateWithFlags(&ev_fork, cudaEventDisableTiming);
        cudaEventCreateWithFlags(&ev_side_done, cudaEventDisableTiming);
    }

    dim3 gemm_grid(CC / 128, MM / 128);   // (8, 64)

    // Fork side stream off the main (legacy) stream.
    cudaEventRecord(ev_fork, 0);
    cudaStreamWaitEvent(s_side, ev_fork, 0);

    // --- side stream: conv/LN/GELU -> heads -> cvt Wout ---
    conv_ln_gelu<<<MM, 256, 0, s_side>>>(x, dw_w, dw_b, ln_g, ln_b, xdw);
    heads_pos<<<MM / 8, 256, 0, s_side>>>(xdw, Wo, bo, Wm, bmv, recw, reci);
    cvt_f16<<<(CC * CC / 4) / 256, 256, 0, s_side>>>(
        (const float4*)Wout, (uint2*)woh, CC * CC / 4);
    cudaEventRecord(ev_side_done, s_side);

    // --- main stream: cvt x, cvt Wi, GEMM1 ---
    cvt_f16<<<(MM * CC / 4) / 256, 256>>>((const float4*)x, (uint2*)xh,
                                          MM * CC / 4);
    cvt_f16<<<(CC * CC / 4) / 256, 256>>>((const float4*)Wi, (uint2*)wih,
                                          CC * CC / 4);
    mma_gemm<__half><<<gemm_grid, 256, SMEM_DYN>>>(xh, wih, bi, xph);

    // Join: C needs xph (main) + records (side); GEMM2 needs woh (side).
    cudaStreamWaitEvent(0, ev_side_done, 0);

    gather_blend<<<MM, 128>>>(xph, recw, reci, samph);
    mma_gemm<float><<<gemm_grid, 256, SMEM_DYN>>>(samph, woh, bout, out);
}

// round 9
// speedup vs baseline: 5.9774x; 1.0945x over previous
#include <cuda_runtime.h>
#include <cuda_fp16.h>
#include <math.h>
#include <stdint.h>

// Problem constants
#define NB   4
#define LL   2048
#define CC   1024
#define KK   7
#define MM   (NB * LL)   // 8192

// Scratch (allocation-free rule: __device__ globals)
__device__ __half g_xh[MM * CC];     // fp16 x (emitted by conv_ln_gelu)
__device__ __half g_wih[CC * CC];    // fp16 Wi
__device__ __half g_woh[CC * CC];    // fp16 Wout
__device__ __half g_xph[MM * CC];    // x_proj (fp16)
__device__ __half g_xdw[MM * CC];    // conv+LN+GELU result (fp16)
__device__ __half g_samph[MM * CC];  // sampled (fp16)
__device__ float  g_recw[MM * 16];   // per-position blend weights (wf[8], wc[8])
__device__ int    g_reci[MM * 16];   // per-position gather indices (pf[8], pc[8])

// ---------------------------------------------------------------------------
// helpers
// ---------------------------------------------------------------------------
__device__ __forceinline__ uint32_t smem_u32(const void* p) {
    uint32_t a;
    asm("{ .reg .u64 t; cvta.to.shared.u64 t, %1; cvt.u32.u64 %0, t; }"
        : "=r"(a) : "l"(p));
    return a;
}

__device__ __forceinline__ void mma_f16(float* d, const uint32_t* a,
                                        const uint32_t* b) {
    asm volatile(
        "mma.sync.aligned.m16n8k16.row.col.f32.f16.f16.f32 "
        "{%0,%1,%2,%3}, {%4,%5,%6,%7}, {%8,%9}, {%0,%1,%2,%3};"
        : "+f"(d[0]), "+f"(d[1]), "+f"(d[2]), "+f"(d[3])
        : "r"(a[0]), "r"(a[1]), "r"(a[2]), "r"(a[3]),
          "r"(b[0]), "r"(b[1]));
}

#define LDSM4(r0, r1, r2, r3, addr)                                           \
    asm volatile("ldmatrix.sync.aligned.m8n8.x4.shared.b16 {%0,%1,%2,%3}, [%4];" \
                 : "=r"(r0), "=r"(r1), "=r"(r2), "=r"(r3) : "r"(addr))

#define CP_ASYNC16(dst, src) \
    asm volatile("cp.async.cg.shared.global [%0], [%1], 16;" :: "r"(dst), "l"(src))
#define CP_COMMIT() asm volatile("cp.async.commit_group;" ::: "memory")
#define CP_WAIT1()  asm volatile("cp.async.wait_group 1;" ::: "memory")

__device__ __forceinline__ void store_out(float2 v, float* p) {
    *(float2*)p = v;
}
__device__ __forceinline__ void store_out(float2 v, __half* p) {
    *(__half2*)p = __floats2half2_rn(v.x, v.y);
}

// ---------------------------------------------------------------------------
// fp32 -> fp16 conversion pre-pass (weights only)
// ---------------------------------------------------------------------------
__global__ __launch_bounds__(256)
void cvt_f16(const float4* __restrict__ in, uint2* __restrict__ out, int n4) {
    int i = blockIdx.x * blockDim.x + threadIdx.x;
    if (i < n4) {
        float4 v = in[i];
        __half2 h0 = __floats2half2_rn(v.x, v.y);
        __half2 h1 = __floats2half2_rn(v.z, v.w);
        uint2 o;
        o.x = *(uint32_t*)&h0;
        o.y = *(uint32_t*)&h1;
        out[i] = o;
    }
}

// ---------------------------------------------------------------------------
// fp16 mma.sync GEMM (NT): C[m,n] = sum_k A[m,k]*B[n,k] + bias[n]
// A,B fp16 [.,1024]; 128x128 CTA tile, BK=64 (128B rows), 8 warps (4x2),
// 32x64 warp tile, 256 threads, 3-stage cp.async, XOR swizzle, ldmatrix.
// Output type templated (fp32 or fp16).
// ---------------------------------------------------------------------------
#define STAGE_BYTES 32768           // A tile 16KB + B tile 16KB
#define SMEM_DYN    (3 * STAGE_BYTES)

__device__ __forceinline__ void stage_in(uint32_t sbase,
                                         const __half* __restrict__ A,
                                         const __half* __restrict__ B,
                                         int bm, int bn, int k0, int tid) {
#pragma unroll
    for (int i = 0; i < 4; ++i) {
        int f = i * 256 + tid;            // 0..1023
        int row = f >> 3, c4 = f & 7;
        uint32_t dst = sbase + row * 128 + ((c4 ^ (row & 7)) << 4);
        const __half* src = A + (size_t)(bm + row) * 1024 + k0 + c4 * 8;
        CP_ASYNC16(dst, src);
    }
#pragma unroll
    for (int i = 0; i < 4; ++i) {
        int f = i * 256 + tid;
        int row = f >> 3, c4 = f & 7;
        uint32_t dst = sbase + 16384 + row * 128 + ((c4 ^ (row & 7)) << 4);
        const __half* src = B + (size_t)(bn + row) * 1024 + k0 + c4 * 8;
        CP_ASYNC16(dst, src);
    }
}

template <typename OT>
__global__ __launch_bounds__(256, 2)
void mma_gemm(const __half* __restrict__ A, const __half* __restrict__ B,
              const float* __restrict__ bias, OT* __restrict__ Cout) {
    extern __shared__ char dyn_smem[];
    const uint32_t sb = smem_u32(dyn_smem);

    const int tid  = threadIdx.x;
    const int wid  = tid >> 5;
    const int lane = tid & 31;
    const int g    = lane >> 2;
    const int tig  = lane & 3;
    const int wm   = wid >> 1;     // 0..3  (32 rows each)
    const int wn   = wid & 1;      // 0..1  (64 cols each)
    const int bm = blockIdx.y * 128;
    const int bn = blockIdx.x * 128;

    float d[2][8][4];
#pragma unroll
    for (int i = 0; i < 2; ++i)
#pragma unroll
        for (int j = 0; j < 8; ++j)
#pragma unroll
            for (int r = 0; r < 4; ++r) d[i][j][r] = 0.f;

    // --- ldmatrix per-thread row addresses (within tile), swizzle keys ---
    const int aHi = (lane >> 4) & 1;
    uint32_t aRowOff[2];
    uint32_t aSw[2];
#pragma unroll
    for (int i = 0; i < 2; ++i) {
        int rowA = wm * 32 + i * 16 + (lane & 15);
        aRowOff[i] = (uint32_t)(rowA * 128);
        aSw[i] = (uint32_t)(rowA & 7);
    }
    const int bHi = (lane >> 3) & 1;
    uint32_t bRowOff[4];
    uint32_t bSw[4];
#pragma unroll
    for (int j2 = 0; j2 < 4; ++j2) {
        int rowB = wn * 64 + j2 * 16 + ((lane & 16) >> 1) + (lane & 7);
        bRowOff[j2] = (uint32_t)(rowB * 128);
        bSw[j2] = (uint32_t)(rowB & 7);
    }

    // prologue
    stage_in(sb + 0 * STAGE_BYTES, A, B, bm, bn, 0, tid);
    CP_COMMIT();
    stage_in(sb + 1 * STAGE_BYTES, A, B, bm, bn, 64, tid);
    CP_COMMIT();

#pragma unroll 1
    for (int s = 0; s < 16; ++s) {
        CP_WAIT1();
        __syncthreads();

        if (s + 2 < 16)
            stage_in(sb + ((s + 2) % 3) * STAGE_BYTES, A, B, bm, bn,
                     (s + 2) * 64, tid);
        CP_COMMIT();

        const uint32_t aBase = sb + (s % 3) * STAGE_BYTES;
        const uint32_t bBase = aBase + 16384u;

#pragma unroll
        for (int ks = 0; ks < 4; ++ks) {
            const uint32_t granA = (uint32_t)(2 * ks + aHi);
            const uint32_t granB = (uint32_t)(2 * ks + bHi);

            uint32_t af[2][4];
#pragma unroll
            for (int i = 0; i < 2; ++i) {
                uint32_t addr = aBase + aRowOff[i] + ((granA ^ aSw[i]) << 4);
                LDSM4(af[i][0], af[i][1], af[i][2], af[i][3], addr);
            }
            uint32_t bf[8][2];
#pragma unroll
            for (int j2 = 0; j2 < 4; ++j2) {
                uint32_t addr = bBase + bRowOff[j2] + ((granB ^ bSw[j2]) << 4);
                LDSM4(bf[2 * j2][0], bf[2 * j2][1],
                      bf[2 * j2 + 1][0], bf[2 * j2 + 1][1], addr);
            }
#pragma unroll
            for (int i = 0; i < 2; ++i)
#pragma unroll
                for (int j = 0; j < 8; ++j)
                    mma_f16(d[i][j], af[i], bf[j]);
        }
    }

    // epilogue: D frag (i,j): rows (g, g+8), cols (2*tig, 2*tig+1)
#pragma unroll
    for (int i = 0; i < 2; ++i) {
        int row = bm + wm * 32 + i * 16 + g;
        OT* o0 = Cout + (size_t)row * 1024 + bn + wn * 64;
        OT* o1 = o0 + 8 * 1024;
#pragma unroll
        for (int j = 0; j < 8; ++j) {
            int col = j * 8 + tig * 2;
            float2 bb = *(const float2*)&bias[bn + wn * 64 + col];
            float2 v0, v1;
            v0.x = d[i][j][0] + bb.x;
            v0.y = d[i][j][1] + bb.y;
            v1.x = d[i][j][2] + bb.x;
            v1.y = d[i][j][3] + bb.y;
            store_out(v0, o0 + col);
            store_out(v1, o1 + col);
        }
    }
}

// ---------------------------------------------------------------------------
// Kernel A: depthwise conv(k=3,pad=1) + LayerNorm + exact GELU -> x_dw fp16,
// and emits fp16 copy of its own x row (fuses the former cvt_x kernel).
// One block (256 thr) per (n,l); 4 channels per thread.
// ---------------------------------------------------------------------------
__global__ __launch_bounds__(256)
void conv_ln_gelu(const float* __restrict__ x,
                  const float* __restrict__ dw_w, const float* __restrict__ dw_b,
                  const float* __restrict__ ln_g, const float* __restrict__ ln_b,
                  __half* __restrict__ xdw, __half* __restrict__ xh) {
    const int nl = blockIdx.x;           // 0..8191
    const int l = nl & (LL - 1);
    const int tid = threadIdx.x;
    const int lane = tid & 31;
    const int wid = tid >> 5;
    const int c0 = tid * 4;

    const float* x0 = x + (size_t)nl * CC;

    float4 xm = *(const float4*)(x0 + c0);
    float4 xl = (l > 0)      ? *(const float4*)(x0 + c0 - CC) : make_float4(0,0,0,0);
    float4 xr = (l < LL - 1) ? *(const float4*)(x0 + c0 + CC) : make_float4(0,0,0,0);

    // emit fp16 copy of this row (feeds GEMM1)
    {
        __half2 hx0 = __floats2half2_rn(xm.x, xm.y);
        __half2 hx1 = __floats2half2_rn(xm.z, xm.w);
        uint2 oxh;
        oxh.x = *(uint32_t*)&hx0;
        oxh.y = *(uint32_t*)&hx1;
        *(uint2*)(xh + (size_t)nl * CC + c0) = oxh;
    }

    float4 db = *(const float4*)(dw_b + c0);
    float v[4];
    {
        const float* wp = dw_w + c0 * 3;
        v[0] = db.x + xl.x * wp[0]  + xm.x * wp[1]  + xr.x * wp[2];
        v[1] = db.y + xl.y * wp[3]  + xm.y * wp[4]  + xr.y * wp[5];
        v[2] = db.z + xl.z * wp[6]  + xm.z * wp[7]  + xr.z * wp[8];
        v[3] = db.w + xl.w * wp[9]  + xm.w * wp[10] + xr.w * wp[11];
    }

    float s  = v[0] + v[1] + v[2] + v[3];
    float s2 = v[0]*v[0] + v[1]*v[1] + v[2]*v[2] + v[3]*v[3];
#pragma unroll
    for (int o = 16; o; o >>= 1) {
        s  += __shfl_xor_sync(0xFFFFFFFFu, s,  o);
        s2 += __shfl_xor_sync(0xFFFFFFFFu, s2, o);
    }
    __shared__ float rs[8], rs2[8];
    __shared__ float stats[2];
    if (lane == 0) { rs[wid] = s; rs2[wid] = s2; }
    __syncthreads();
    if (tid == 0) {
        float S = 0.f, S2 = 0.f;
#pragma unroll
        for (int w = 0; w < 8; ++w) { S += rs[w]; S2 += rs2[w]; }
        float mu = S * (1.f / CC);
        float var = S2 * (1.f / CC) - mu * mu;
        stats[0] = mu;
        stats[1] = rsqrtf(var + 1e-5f);
    }
    __syncthreads();
    const float mu = stats[0], rstd = stats[1];

    float4 lg = *(const float4*)(ln_g + c0);
    float4 lb = *(const float4*)(ln_b + c0);
    float g0, g1, g2, g3, h;
    h = (v[0] - mu) * rstd * lg.x + lb.x;
    g0 = 0.5f * h * (1.f + erff(h * 0.70710678118654752f));
    h = (v[1] - mu) * rstd * lg.y + lb.y;
    g1 = 0.5f * h * (1.f + erff(h * 0.70710678118654752f));
    h = (v[2] - mu) * rstd * lg.z + lb.z;
    g2 = 0.5f * h * (1.f + erff(h * 0.70710678118654752f));
    h = (v[3] - mu) * rstd * lg.w + lb.w;
    g3 = 0.5f * h * (1.f + erff(h * 0.70710678118654752f));

    __half2 h0 = __floats2half2_rn(g0, g1);
    __half2 h1 = __floats2half2_rn(g2, g3);
    uint2 ov;
    ov.x = *(uint32_t*)&h0;
    ov.y = *(uint32_t*)&h1;
    *(uint2*)(xdw + (size_t)nl * CC + c0) = ov;
}

// ---------------------------------------------------------------------------
// Kernel B: offset/mask heads + softmax + positions -> gather records.
// Warp per position, 8 positions per block, no __syncthreads.
// ---------------------------------------------------------------------------
__global__ __launch_bounds__(256)
void heads_pos(const __half* __restrict__ xdw,
               const float* __restrict__ Wo, const float* __restrict__ bo,
               const float* __restrict__ Wm, const float* __restrict__ bmv,
               float* __restrict__ recw, int* __restrict__ reci) {
    const int wid  = threadIdx.x >> 5;
    const int lane = threadIdx.x & 31;
    const int pos  = blockIdx.x * 8 + wid;
    const int l    = pos & (LL - 1);

    const __half2* xr = (const __half2*)(xdw + (size_t)pos * CC);

    float p[14];
#pragma unroll
    for (int j = 0; j < 14; ++j) p[j] = 0.f;

#pragma unroll
    for (int i = 0; i < 16; ++i) {
        __half2 hv = xr[lane + 32 * i];
        float2 f = __half22float2(hv);
        int c = 2 * (lane + 32 * i);
#pragma unroll
        for (int j = 0; j < 7; ++j) {
            float2 w1 = *(const float2*)(Wo + j * CC + c);
            float2 w2 = *(const float2*)(Wm + j * CC + c);
            p[j]     = fmaf(f.x, w1.x, fmaf(f.y, w1.y, p[j]));
            p[7 + j] = fmaf(f.x, w2.x, fmaf(f.y, w2.y, p[7 + j]));
        }
    }
#pragma unroll
    for (int o = 16; o; o >>= 1)
#pragma unroll
        for (int j = 0; j < 14; ++j)
            p[j] += __shfl_xor_sync(0xFFFFFFFFu, p[j], o);

    if (lane == 0) {
        float ho[KK], hm[KK];
#pragma unroll
        for (int j = 0; j < KK; ++j) {
            ho[j] = (p[j] + bo[j]) * 2.0f;     // OFFSET_SCALE
            hm[j] = p[7 + j] + bmv[j];
        }
        float mx = hm[0];
#pragma unroll
        for (int j = 1; j < KK; ++j) mx = fmaxf(mx, hm[j]);
        float e[KK], se = 0.f;
#pragma unroll
        for (int j = 0; j < KK; ++j) { e[j] = expf(hm[j] - mx); se += e[j]; }
        float inv = 1.f / se;

        float* rw = recw + (size_t)pos * 16;
        int*   ri = reci + (size_t)pos * 16;
#pragma unroll
        for (int k = 0; k < KK; ++k) {
            float mask = e[k] * inv;
            float ap  = (float)l + (float)(k - 3) + ho[k];
            float apc = fminf(fmaxf(ap, 0.f), (float)(LL - 1));
            int pf = (int)apc;
            if (pf > LL - 1) pf = LL - 1;
            int pc = pf + 1; if (pc > LL - 1) pc = LL - 1;
            float wc = apc - (float)pf;
            float wf = 1.f - wc;
            float valid = (ap < 0.f || ap > (float)(LL - 1)) ? 0.f : 1.f;
            rw[k]     = wf * valid * mask;
            rw[8 + k] = wc * valid * mask;
            ri[k]     = pf;
            ri[8 + k] = pc;
        }
    }
}

// ---------------------------------------------------------------------------
// Kernel C: gather-blend from fp16 x_proj -> sampled fp16.
// One block (128 thr) per position, 8 channels per thread, no __syncthreads.
// ---------------------------------------------------------------------------
__global__ __launch_bounds__(128)
void gather_blend(const __half* __restrict__ xph,
                  const float* __restrict__ recw, const int* __restrict__ reci,
                  __half* __restrict__ samp) {
    const int nl = blockIdx.x;
    const int n  = nl >> 11;
    const int c0 = threadIdx.x * 8;

    const float* rw = recw + (size_t)nl * 16;
    const int*   ri = reci + (size_t)nl * 16;

    float wf[KK], wc[KK];
    int   pf[KK], pc[KK];
#pragma unroll
    for (int k = 0; k < KK; ++k) {
        wf[k] = __ldg(rw + k);
        wc[k] = __ldg(rw + 8 + k);
        pf[k] = __ldg(ri + k);
        pc[k] = __ldg(ri + 8 + k);
    }

    const __half* xpn = xph + (size_t)n * LL * CC + c0;

    float acc[8];
#pragma unroll
    for (int m = 0; m < 8; ++m) acc[m] = 0.f;

#pragma unroll
    for (int k = 0; k < KK; ++k) {
        uint4 rf = *(const uint4*)(xpn + (size_t)pf[k] * CC);
        uint4 rc = *(const uint4*)(xpn + (size_t)pc[k] * CC);
        float w0 = wf[k], w1 = wc[k];
        const __half2* hf = (const __half2*)&rf;
        const __half2* hc = (const __half2*)&rc;
#pragma unroll
        for (int m = 0; m < 4; ++m) {
            float2 ff = __half22float2(hf[m]);
            float2 fc = __half22float2(hc[m]);
            acc[2*m + 0] = fmaf(ff.x, w0, fmaf(fc.x, w1, acc[2*m + 0]));
            acc[2*m + 1] = fmaf(ff.y, w0, fmaf(fc.y, w1, acc[2*m + 1]));
        }
    }

    uint4 ov;
    __half2 o0 = __floats2half2_rn(acc[0], acc[1]);
    __half2 o1 = __floats2half2_rn(acc[2], acc[3]);
    __half2 o2 = __floats2half2_rn(acc[4], acc[5]);
    __half2 o3 = __floats2half2_rn(acc[6], acc[7]);
    ov.x = *(uint32_t*)&o0; ov.y = *(uint32_t*)&o1;
    ov.z = *(uint32_t*)&o2; ov.w = *(uint32_t*)&o3;
    *(uint4*)(samp + (size_t)nl * CC + c0) = ov;
}

// ---------------------------------------------------------------------------
// Launch — restructured schedule:
//
//   main: cvt_wi -> A(x->xh,xdw) -[evA]-> GEMM1 -[wait evB]-> C -> GEMM2
//   side: cvt_wo ------[wait evA]-> B -[evB]
//
// B (L1-bound, 20us) hides under GEMM1 (tensor-bound); side stream is
// low-priority so GEMM1 wins the CTA scheduler.
// ---------------------------------------------------------------------------
extern "C" void kernel_launch(void* const* d_in, const int* in_sizes, int n_in,
                              void* d_out, int out_size) {
    const float* x    = (const float*)d_in[0];
    const float* Wi   = (const float*)d_in[1];
    const float* bi   = (const float*)d_in[2];
    const float* dw_w = (const float*)d_in[3];
    const float* dw_b = (const float*)d_in[4];
    const float* ln_g = (const float*)d_in[5];
    const float* ln_b = (const float*)d_in[6];
    const float* Wo   = (const float*)d_in[7];
    const float* bo   = (const float*)d_in[8];
    const float* Wm   = (const float*)d_in[9];
    const float* bmv  = (const float*)d_in[10];
    const float* Wout = (const float*)d_in[11];
    const float* bout = (const float*)d_in[12];
    float* out = (float*)d_out;

    __half *xh, *wih, *woh, *xph, *xdw, *samph;
    float *recw;
    int *reci;
    cudaGetSymbolAddress((void**)&xh,    g_xh);
    cudaGetSymbolAddress((void**)&wih,   g_wih);
    cudaGetSymbolAddress((void**)&woh,   g_woh);
    cudaGetSymbolAddress((void**)&xph,   g_xph);
    cudaGetSymbolAddress((void**)&xdw,   g_xdw);
    cudaGetSymbolAddress((void**)&samph, g_samph);
    cudaGetSymbolAddress((void**)&recw,  g_recw);
    cudaGetSymbolAddress((void**)&reci,  g_reci);

    cudaFuncSetAttribute(mma_gemm<__half>,
                         cudaFuncAttributeMaxDynamicSharedMemorySize, SMEM_DYN);
    cudaFuncSetAttribute(mma_gemm<float>,
                         cudaFuncAttributeMaxDynamicSharedMemorySize, SMEM_DYN);

    // One-time host-side stream/event creation (no device memory involved).
    static cudaStream_t s_side = nullptr;
    static cudaEvent_t  ev_fork = nullptr, ev_a = nullptr, ev_b = nullptr;
    if (s_side == nullptr) {
        int lo = 0, hi = 0;
        cudaDeviceGetStreamPriorityRange(&lo, &hi);   // lo = lowest priority
        cudaStreamCreateWithPriority(&s_side, cudaStreamNonBlocking, lo);
        cudaEventCreateWithFlags(&ev_fork, cudaEventDisableTiming);
        cudaEventCreateWithFlags(&ev_a,    cudaEventDisableTiming);
        cudaEventCreateWithFlags(&ev_b,    cudaEventDisableTiming);
    }

    dim3 gemm_grid(CC / 128, MM / 128);   // (8, 64)

    // Fork side stream off the main (legacy) stream.
    cudaEventRecord(ev_fork, 0);
    cudaStreamWaitEvent(s_side, ev_fork, 0);

    // side: cvt Wout at t=0 (tiny, DRAM-bound)
    cvt_f16<<<(CC * CC / 4) / 256, 256, 0, s_side>>>(
        (const float4*)Wout, (uint2*)woh, CC * CC / 4);

    // main: cvt Wi, then A (emits xh + xdw)
    cvt_f16<<<(CC * CC / 4) / 256, 256>>>((const float4*)Wi, (uint2*)wih,
                                          CC * CC / 4);
    conv_ln_gelu<<<MM, 256>>>(x, dw_w, dw_b, ln_g, ln_b, xdw, xh);
    cudaEventRecord(ev_a, 0);

    // side: B after A (needs xdw)
    cudaStreamWaitEvent(s_side, ev_a, 0);
    heads_pos<<<MM / 8, 256, 0, s_side>>>(xdw, Wo, bo, Wm, bmv, recw, reci);
    cudaEventRecord(ev_b, s_side);

    // main: GEMM1 (overlaps B), then join, C, GEMM2
    mma_gemm<__half><<<gemm_grid, 256, SMEM_DYN>>>(xh, wih, bi, xph);
    cudaStreamWaitEvent(0, ev_b, 0);
    gather_blend<<<MM, 128>>>(xph, recw, reci, samph);
    mma_gemm<float><<<gemm_grid, 256, SMEM_DYN>>>(samph, woh, bout, out);
}